// round 1
// baseline (speedup 1.0000x reference)
#include <cuda_runtime.h>
#include <cstddef>

#define NN   50000
#define NE   640000
#define INF_ 512
#define HIDF 128
#define NG   256

// ---------------- device scratch (no allocations allowed) ----------------
__device__ int   g_cnt[NN];
__device__ float g_dinv[NN];
__device__ int   g_rowptr[NN + 1];
__device__ int   g_cursor[NN];
__device__ int   g_src[NE];
__device__ float g_bufA[(size_t)NN * HIDF];
__device__ float g_bufB[(size_t)NN * HIDF];

// ---------------- graph preprocessing ----------------
__global__ void k_init() {
    int i = blockIdx.x * blockDim.x + threadIdx.x;
    if (i < NN) g_cnt[i] = 0;
}

__global__ void k_count(const int* __restrict__ col) {
    int e = blockIdx.x * blockDim.x + threadIdx.x;
    if (e < NE) atomicAdd(&g_cnt[col[e]], 1);
}

// single-block exclusive scan of g_cnt -> g_rowptr / g_cursor, plus dinv
__global__ void k_scan() {
    __shared__ int sh[1024];
    __shared__ int carry_s;
    int tid = threadIdx.x;
    if (tid == 0) carry_s = 0;
    __syncthreads();
    for (int base = 0; base < NN; base += 1024) {
        int idx = base + tid;
        int v = (idx < NN) ? g_cnt[idx] : 0;
        sh[tid] = v;
        __syncthreads();
        #pragma unroll
        for (int off = 1; off < 1024; off <<= 1) {
            int t = (tid >= off) ? sh[tid - off] : 0;
            __syncthreads();
            sh[tid] += t;
            __syncthreads();
        }
        int excl  = sh[tid] - v;
        int carry = carry_s;
        if (idx < NN) {
            int rp = carry + excl;
            g_rowptr[idx] = rp;
            g_cursor[idx] = rp;
            g_dinv[idx]   = rsqrtf((float)(v + 1));  // +1 self-loop
        }
        __syncthreads();
        if (tid == 0) carry_s = carry + sh[1023];
        __syncthreads();
    }
    if (tid == 0) g_rowptr[NN] = carry_s;
}

__global__ void k_fill(const int* __restrict__ row, const int* __restrict__ col) {
    int e = blockIdx.x * blockDim.x + threadIdx.x;
    if (e < NE) {
        int d = col[e];
        int p = atomicAdd(&g_cursor[d], 1);
        g_src[p] = row[e];
    }
}

// ---------------- fp32 SGEMM: C[M,N] = A[M,K] @ B[K,N], N == 128 ----------------
// BM=128, BN=128, BK=16, 256 threads, 8x8 per thread
__global__ __launch_bounds__(256) void sgemm128(const float* __restrict__ A,
                                                const float* __restrict__ B,
                                                float* __restrict__ C,
                                                int M, int K) {
    const int BM = 128, BN = 128, BK = 16, TM = 8, TN = 8;
    __shared__ float As[BK][BM];
    __shared__ float Bs[BK][BN];
    int tid = threadIdx.x;
    int rowBase = blockIdx.x * BM;
    int tcol = tid % (BN / TN);   // 0..15
    int trow = tid / (BN / TN);   // 0..15
    float acc[TM][TN];
    #pragma unroll
    for (int i = 0; i < TM; i++)
        #pragma unroll
        for (int j = 0; j < TN; j++) acc[i][j] = 0.f;

    for (int k0 = 0; k0 < K; k0 += BK) {
        // load A tile 128x16 (512 float4, 2 per thread), transpose into As[k][m]
        #pragma unroll
        for (int l = 0; l < 2; l++) {
            int i  = tid * 2 + l;
            int r  = i >> 2;
            int kc = (i & 3) * 4;
            float4 v = make_float4(0.f, 0.f, 0.f, 0.f);
            int gr = rowBase + r;
            if (gr < M) v = *(const float4*)(A + (size_t)gr * K + k0 + kc);
            As[kc + 0][r] = v.x; As[kc + 1][r] = v.y;
            As[kc + 2][r] = v.z; As[kc + 3][r] = v.w;
        }
        // load B tile 16x128 (512 float4, 2 per thread)
        #pragma unroll
        for (int l = 0; l < 2; l++) {
            int i = tid * 2 + l;
            int r = i >> 5;
            int c = (i & 31) * 4;
            *(float4*)(&Bs[r][c]) = *(const float4*)(B + (size_t)(k0 + r) * BN + c);
        }
        __syncthreads();
        #pragma unroll
        for (int kk = 0; kk < BK; kk++) {
            float a[TM], b[TN];
            #pragma unroll
            for (int i = 0; i < TM; i++) a[i] = As[kk][trow * TM + i];
            #pragma unroll
            for (int j = 0; j < TN; j++) b[j] = Bs[kk][tcol * TN + j];
            #pragma unroll
            for (int i = 0; i < TM; i++)
                #pragma unroll
                for (int j = 0; j < TN; j++) acc[i][j] += a[i] * b[j];
        }
        __syncthreads();
    }
    #pragma unroll
    for (int i = 0; i < TM; i++) {
        int gr = rowBase + trow * TM + i;
        if (gr >= M) continue;
        #pragma unroll
        for (int j = 0; j < TN; j += 4) {
            float4 v = make_float4(acc[i][j], acc[i][j + 1], acc[i][j + 2], acc[i][j + 3]);
            *(float4*)(C + (size_t)gr * BN + tcol * TN + j) = v;
        }
    }
}

// ---------------- GCN aggregation: one warp per node, CSR gather ----------------
__global__ __launch_bounds__(256) void k_agg(const float* __restrict__ in,
                                             float* __restrict__ out,
                                             const float* __restrict__ bias,
                                             int do_relu) {
    int warp = (blockIdx.x * blockDim.x + threadIdx.x) >> 5;
    int lane = threadIdx.x & 31;
    if (warp >= NN) return;
    float dn = g_dinv[warp];
    // self-loop contribution
    float4 v = ((const float4*)(in + (size_t)warp * HIDF))[lane];
    float s = dn * dn;
    float4 acc = make_float4(v.x * s, v.y * s, v.z * s, v.w * s);
    int beg = g_rowptr[warp], end = g_rowptr[warp + 1];
    for (int j = beg; j < end; j++) {
        int src = g_src[j];                    // broadcast load
        float w = g_dinv[src] * dn;            // broadcast load
        float4 u = ((const float4*)(in + (size_t)src * HIDF))[lane];
        acc.x += u.x * w; acc.y += u.y * w;
        acc.z += u.z * w; acc.w += u.w * w;
    }
    float4 b = ((const float4*)bias)[lane];
    acc.x += b.x; acc.y += b.y; acc.z += b.z; acc.w += b.w;
    if (do_relu) {
        acc.x = fmaxf(acc.x, 0.f); acc.y = fmaxf(acc.y, 0.f);
        acc.z = fmaxf(acc.z, 0.f); acc.w = fmaxf(acc.w, 0.f);
    }
    ((float4*)(out + (size_t)warp * HIDF))[lane] = acc;
}

// ---------------- global_add_pool: batch is sorted -> segmented sum ----------------
__global__ void k_pool(const float* __restrict__ h, const int* __restrict__ batch,
                       float* __restrict__ out) {
    int g = blockIdx.x;        // 0..255
    int t = threadIdx.x;       // 0..127
    // lower_bound(batch, g) / lower_bound(batch, g+1)
    int a = 0, b = NN;
    while (a < b) { int m = (a + b) >> 1; if (batch[m] < g) a = m + 1; else b = m; }
    int s = a;
    a = 0; b = NN;
    while (a < b) { int m = (a + b) >> 1; if (batch[m] < g + 1) a = m + 1; else b = m; }
    int e = a;
    float acc = 0.f;
    for (int n = s; n < e; n++) acc += h[(size_t)n * HIDF + t];
    out[(size_t)g * HIDF + t] = acc;
}

// ---------------- launch ----------------
extern "C" void kernel_launch(void* const* d_in, const int* in_sizes, int n_in,
                              void* d_out, int out_size) {
    const float* x     = (const float*)d_in[0];
    const float* W1    = (const float*)d_in[1];
    const float* b1    = (const float*)d_in[2];
    const float* W2    = (const float*)d_in[3];
    const float* b2    = (const float*)d_in[4];
    const int*   ei    = (const int*)d_in[5];
    const int*   batch = (const int*)d_in[6];
    const int* row = ei;            // edge_index[0] = source
    const int* col = ei + NE;       // edge_index[1] = target

    float* out_hs = (float*)d_out;                  // [256,128]
    float* out_h  = (float*)d_out + (size_t)NG * HIDF;  // [50000,128]

    float *bufA, *bufB;
    cudaGetSymbolAddress((void**)&bufA, g_bufA);
    cudaGetSymbolAddress((void**)&bufB, g_bufB);

    // graph structure
    k_init <<<(NN + 255) / 256, 256>>>();
    k_count<<<(NE + 255) / 256, 256>>>(col);
    k_scan <<<1, 1024>>>();
    k_fill <<<(NE + 255) / 256, 256>>>(row, col);

    const int GEMM_GRID = (NN + 127) / 128;   // 391
    const int AGG_GRID  = (NN + 7) / 8;       // 6250

    // layer 1: h1 = x @ W1 ; agg + b1 ; relu
    sgemm128<<<GEMM_GRID, 256>>>(x, W1, bufA, NN, INF_);
    k_agg<<<AGG_GRID, 256>>>(bufA, bufB, b1, 1);

    // layer 2: h2 = h @ W2 ; agg + b2
    sgemm128<<<GEMM_GRID, 256>>>(bufB, W2, bufA, NN, HIDF);
    k_agg<<<AGG_GRID, 256>>>(bufA, out_h, b2, 0);

    // pooling
    k_pool<<<NG, 128>>>(out_h, batch, out_hs);
}

// round 3
// speedup vs baseline: 1.3552x; 1.3552x over previous
#include <cuda_runtime.h>
#include <cuda_bf16.h>
#include <cstdint>
#include <cstddef>

#define NN   50000
#define NE   640000
#define INF_ 512
#define HIDF 128
#define NG   256

// ---------------- device scratch (no allocations allowed) ----------------
__device__ int   g_cnt[NN];
__device__ float g_dinv[NN];
__device__ int   g_rowptr[NN + 1];
__device__ int   g_cursor[NN];
__device__ int   g_src[NE];
__device__ float g_bufA[(size_t)NN * HIDF];
__device__ float g_bufB[(size_t)NN * HIDF];
// transposed bf16 hi/lo weights: Wt[n][k] = W[k][n]
__device__ __nv_bfloat16 g_w1h[128 * 512];
__device__ __nv_bfloat16 g_w1l[128 * 512];
__device__ __nv_bfloat16 g_w2h[128 * 128];
__device__ __nv_bfloat16 g_w2l[128 * 128];

// ---------------- helpers ----------------
__device__ __forceinline__ uint32_t smem_u32(const void* p) {
    uint32_t a;
    asm("{ .reg .u64 t; cvta.to.shared.u64 t, %1; cvt.u32.u64 %0, t; }" : "=r"(a) : "l"(p));
    return a;
}
__device__ __forceinline__ void ldsm_x4(uint32_t& r0, uint32_t& r1, uint32_t& r2, uint32_t& r3,
                                        uint32_t addr) {
    asm volatile("ldmatrix.sync.aligned.m8n8.x4.shared.b16 {%0,%1,%2,%3}, [%4];"
                 : "=r"(r0), "=r"(r1), "=r"(r2), "=r"(r3) : "r"(addr));
}
__device__ __forceinline__ void mma_bf16(float* c, const uint32_t* a, const uint32_t* b) {
    asm volatile(
        "mma.sync.aligned.m16n8k16.row.col.f32.bf16.bf16.f32 "
        "{%0,%1,%2,%3}, {%4,%5,%6,%7}, {%8,%9}, {%0,%1,%2,%3};"
        : "+f"(c[0]), "+f"(c[1]), "+f"(c[2]), "+f"(c[3])
        : "r"(a[0]), "r"(a[1]), "r"(a[2]), "r"(a[3]), "r"(b[0]), "r"(b[1]));
}

// ---------------- graph preprocessing ----------------
__global__ void k_init() {
    int i = blockIdx.x * blockDim.x + threadIdx.x;
    if (i < NN) g_cnt[i] = 0;
}

__global__ void k_count(const int* __restrict__ col) {
    int e = blockIdx.x * blockDim.x + threadIdx.x;
    if (e < NE) atomicAdd(&g_cnt[col[e]], 1);
}

// 1024-thread single-block scan: segment-per-thread + 2-level warp scan
__global__ __launch_bounds__(1024) void k_scan() {
    __shared__ int wsum[32];
    const int SEG = (NN + 1023) / 1024;  // 49
    int t = threadIdx.x, lane = t & 31, w = t >> 5;
    int s0 = t * SEG, s1 = s0 + SEG;
    if (s1 > NN) s1 = NN;
    if (s0 > NN) s0 = NN;
    int s = 0;
    for (int i = s0; i < s1; i++) s += g_cnt[i];
    int v = s;
    #pragma unroll
    for (int o = 1; o < 32; o <<= 1) {
        int u = __shfl_up_sync(0xFFFFFFFFu, v, o);
        if (lane >= o) v += u;
    }
    if (lane == 31) wsum[w] = v;
    __syncthreads();
    if (w == 0) {
        int x = wsum[lane];
        #pragma unroll
        for (int o = 1; o < 32; o <<= 1) {
            int u = __shfl_up_sync(0xFFFFFFFFu, x, o);
            if (lane >= o) x += u;
        }
        wsum[lane] = x;
    }
    __syncthreads();
    int P = v - s + (w > 0 ? wsum[w - 1] : 0);
    for (int i = s0; i < s1; i++) {
        int c = g_cnt[i];
        g_rowptr[i] = P;
        g_cursor[i] = P;
        g_dinv[i] = rsqrtf((float)(c + 1));  // +1 self-loop
        P += c;
    }
    if (t == 1023) g_rowptr[NN] = wsum[31];
}

__global__ void k_fill(const int* __restrict__ row, const int* __restrict__ col) {
    int e = blockIdx.x * blockDim.x + threadIdx.x;
    if (e < NE) {
        int d = col[e];
        int p = atomicAdd(&g_cursor[d], 1);
        g_src[p] = row[e];
    }
}

// transpose + bf16 hi/lo split of W1, W2
__global__ void k_prepw(const float* __restrict__ W1, const float* __restrict__ W2) {
    int i = blockIdx.x * blockDim.x + threadIdx.x;
    if (i < 128 * 512) {
        int n = i >> 9, k = i & 511;
        float v = W1[k * 128 + n];
        __nv_bfloat16 h = __float2bfloat16_rn(v);
        g_w1h[i] = h;
        g_w1l[i] = __float2bfloat16_rn(v - __bfloat162float(h));
    }
    if (i < 128 * 128) {
        int n = i >> 7, k = i & 127;
        float v = W2[k * 128 + n];
        __nv_bfloat16 h = __float2bfloat16_rn(v);
        g_w2h[i] = h;
        g_w2l[i] = __float2bfloat16_rn(v - __bfloat162float(h));
    }
}

// ---------------- HMMA GEMM: C[M,128] = A[M,K] @ Wt^T, split-bf16 3-term ----------------
// BM=128, BN=128, BK=32, 256 threads, warp tile 32x64.
// smem tiles padded to 80B rows -> conflict-free ldmatrix.
#define ASTRIDE 40  // bf16 elems per smem row (80 B)

__global__ __launch_bounds__(256) void gemm_mma(const float* __restrict__ A,
                                                const __nv_bfloat16* __restrict__ Bh,
                                                const __nv_bfloat16* __restrict__ Bl,
                                                float* __restrict__ C,
                                                int M, int K) {
    __shared__ __nv_bfloat16 sAh[128 * ASTRIDE];
    __shared__ __nv_bfloat16 sAl[128 * ASTRIDE];
    __shared__ __nv_bfloat16 sBh[128 * ASTRIDE];
    __shared__ __nv_bfloat16 sBl[128 * ASTRIDE];

    const int tid = threadIdx.x;
    const int wid = tid >> 5, lane = tid & 31;
    const int wm = (wid >> 1) * 32;     // warp m offset
    const int wn = (wid & 1) * 64;      // warp n offset
    const int g = lane >> 2, tig = lane & 3;
    const int row0 = blockIdx.x * 128;

    const uint32_t uAh = smem_u32(sAh), uAl = smem_u32(sAl);
    const uint32_t uBh = smem_u32(sBh), uBl = smem_u32(sBl);

    float c[2][8][4];
    #pragma unroll
    for (int mt = 0; mt < 2; mt++)
        #pragma unroll
        for (int nt = 0; nt < 8; nt++)
            #pragma unroll
            for (int q = 0; q < 4; q++) c[mt][nt][q] = 0.f;

    const int nch = K >> 5;  // BK = 32

    // prefetch registers
    float4 pa[4];
    uint4 pbh[2], pbl[2];

    // ---- load chunk 0 ----
    {
        #pragma unroll
        for (int i = 0; i < 4; i++) {
            int q = i * 256 + tid;
            int r = q >> 3, c4 = q & 7;
            int gr = row0 + r;
            pa[i] = (gr < M) ? *(const float4*)(A + (size_t)gr * K + c4 * 4)
                             : make_float4(0.f, 0.f, 0.f, 0.f);
        }
        #pragma unroll
        for (int i = 0; i < 2; i++) {
            int q = i * 256 + tid;
            int r = q >> 2, c16 = q & 3;
            pbh[i] = *(const uint4*)(Bh + (size_t)r * K + c16 * 8);
            pbl[i] = *(const uint4*)(Bl + (size_t)r * K + c16 * 8);
        }
    }

    for (int ch = 0; ch < nch; ch++) {
        // ---- store prefetched chunk to smem (convert A fp32 -> bf16 hi/lo) ----
        #pragma unroll
        for (int i = 0; i < 4; i++) {
            int q = i * 256 + tid;
            int r = q >> 3, c4 = q & 7;
            float4 v = pa[i];
            __nv_bfloat16 hx = __float2bfloat16_rn(v.x);
            __nv_bfloat16 hy = __float2bfloat16_rn(v.y);
            __nv_bfloat16 hz = __float2bfloat16_rn(v.z);
            __nv_bfloat16 hw = __float2bfloat16_rn(v.w);
            __nv_bfloat162 h0; h0.x = hx; h0.y = hy;
            __nv_bfloat162 h1; h1.x = hz; h1.y = hw;
            __nv_bfloat162 l0, l1;
            l0.x = __float2bfloat16_rn(v.x - __bfloat162float(hx));
            l0.y = __float2bfloat16_rn(v.y - __bfloat162float(hy));
            l1.x = __float2bfloat16_rn(v.z - __bfloat162float(hz));
            l1.y = __float2bfloat16_rn(v.w - __bfloat162float(hw));
            int e = r * ASTRIDE + c4 * 4;
            *(uint32_t*)((char*)sAh + e * 2)     = *(uint32_t*)&h0;
            *(uint32_t*)((char*)sAh + e * 2 + 4) = *(uint32_t*)&h1;
            *(uint32_t*)((char*)sAl + e * 2)     = *(uint32_t*)&l0;
            *(uint32_t*)((char*)sAl + e * 2 + 4) = *(uint32_t*)&l1;
        }
        #pragma unroll
        for (int i = 0; i < 2; i++) {
            int q = i * 256 + tid;
            int r = q >> 2, c16 = q & 3;
            int e = r * ASTRIDE + c16 * 8;
            *(uint4*)((char*)sBh + e * 2) = pbh[i];
            *(uint4*)((char*)sBl + e * 2) = pbl[i];
        }
        __syncthreads();

        // ---- issue global loads for next chunk (overlap with mma) ----
        if (ch + 1 < nch) {
            int k0 = (ch + 1) << 5;
            #pragma unroll
            for (int i = 0; i < 4; i++) {
                int q = i * 256 + tid;
                int r = q >> 3, c4 = q & 7;
                int gr = row0 + r;
                pa[i] = (gr < M) ? *(const float4*)(A + (size_t)gr * K + k0 + c4 * 4)
                                 : make_float4(0.f, 0.f, 0.f, 0.f);
            }
            #pragma unroll
            for (int i = 0; i < 2; i++) {
                int q = i * 256 + tid;
                int r = q >> 2, c16 = q & 3;
                pbh[i] = *(const uint4*)(Bh + (size_t)r * K + k0 + c16 * 8);
                pbl[i] = *(const uint4*)(Bl + (size_t)r * K + k0 + c16 * 8);
            }
        }

        // ---- compute: 2 ksteps of k16 ----
        #pragma unroll
        for (int ks = 0; ks < 2; ks++) {
            const int kc = ks * 16 + ((lane & 16) ? 8 : 0);   // A k-col for this lane
            uint32_t ah[2][4], al[2][4];
            #pragma unroll
            for (int mt = 0; mt < 2; mt++) {
                int r = wm + mt * 16 + (lane & 15);
                uint32_t off = (uint32_t)(r * ASTRIDE + kc) * 2;
                ldsm_x4(ah[mt][0], ah[mt][1], ah[mt][2], ah[mt][3], uAh + off);
                ldsm_x4(al[mt][0], al[mt][1], al[mt][2], al[mt][3], uAl + off);
            }
            uint32_t bh[8][2], bl[8][2];
            const int kcb = ks * 16 + ((lane & 8) ? 8 : 0);   // B k-col for this lane
            #pragma unroll
            for (int nt4 = 0; nt4 < 4; nt4++) {
                int n = wn + nt4 * 16 + ((lane & 7) | ((lane & 16) ? 8 : 0));
                uint32_t off = (uint32_t)(n * ASTRIDE + kcb) * 2;
                ldsm_x4(bh[2 * nt4][0], bh[2 * nt4][1], bh[2 * nt4 + 1][0], bh[2 * nt4 + 1][1],
                        uBh + off);
                ldsm_x4(bl[2 * nt4][0], bl[2 * nt4][1], bl[2 * nt4 + 1][0], bl[2 * nt4 + 1][1],
                        uBl + off);
            }
            #pragma unroll
            for (int mt = 0; mt < 2; mt++)
                #pragma unroll
                for (int nt = 0; nt < 8; nt++) {
                    mma_bf16(c[mt][nt], ah[mt], bh[nt]);
                    mma_bf16(c[mt][nt], al[mt], bh[nt]);
                    mma_bf16(c[mt][nt], ah[mt], bl[nt]);
                }
        }
        __syncthreads();
    }

    // ---- epilogue ----
    #pragma unroll
    for (int mt = 0; mt < 2; mt++) {
        int gr0 = row0 + wm + mt * 16 + g;
        int gr1 = gr0 + 8;
        #pragma unroll
        for (int nt = 0; nt < 8; nt++) {
            int cc = wn + nt * 8 + 2 * tig;
            if (gr0 < M) *(float2*)(C + (size_t)gr0 * 128 + cc) = make_float2(c[mt][nt][0], c[mt][nt][1]);
            if (gr1 < M) *(float2*)(C + (size_t)gr1 * 128 + cc) = make_float2(c[mt][nt][2], c[mt][nt][3]);
        }
    }
}

// ---------------- GCN aggregation: one warp per node, CSR gather ----------------
__global__ __launch_bounds__(256) void k_agg(const float* __restrict__ in,
                                             float* __restrict__ out,
                                             const float* __restrict__ bias,
                                             int do_relu) {
    int warp = (blockIdx.x * blockDim.x + threadIdx.x) >> 5;
    int lane = threadIdx.x & 31;
    if (warp >= NN) return;
    float dn = g_dinv[warp];
    float4 v = ((const float4*)(in + (size_t)warp * HIDF))[lane];
    float s = dn * dn;
    float4 acc = make_float4(v.x * s, v.y * s, v.z * s, v.w * s);
    int beg = g_rowptr[warp], end = g_rowptr[warp + 1];
    for (int j = beg; j < end; j++) {
        int src = g_src[j];
        float w = g_dinv[src] * dn;
        float4 u = ((const float4*)(in + (size_t)src * HIDF))[lane];
        acc.x += u.x * w; acc.y += u.y * w;
        acc.z += u.z * w; acc.w += u.w * w;
    }
    float4 b = ((const float4*)bias)[lane];
    acc.x += b.x; acc.y += b.y; acc.z += b.z; acc.w += b.w;
    if (do_relu) {
        acc.x = fmaxf(acc.x, 0.f); acc.y = fmaxf(acc.y, 0.f);
        acc.z = fmaxf(acc.z, 0.f); acc.w = fmaxf(acc.w, 0.f);
    }
    ((float4*)(out + (size_t)warp * HIDF))[lane] = acc;
}

// ---------------- global_add_pool: batch is sorted -> segmented sum ----------------
__global__ void k_pool(const float* __restrict__ h, const int* __restrict__ batch,
                       float* __restrict__ out) {
    int g = blockIdx.x;
    int t = threadIdx.x;
    int a = 0, b = NN;
    while (a < b) { int m = (a + b) >> 1; if (batch[m] < g) a = m + 1; else b = m; }
    int s = a;
    a = 0; b = NN;
    while (a < b) { int m = (a + b) >> 1; if (batch[m] < g + 1) a = m + 1; else b = m; }
    int e = a;
    float acc = 0.f;
    for (int n = s; n < e; n++) acc += h[(size_t)n * HIDF + t];
    out[(size_t)g * HIDF + t] = acc;
}

// ---------------- launch ----------------
extern "C" void kernel_launch(void* const* d_in, const int* in_sizes, int n_in,
                              void* d_out, int out_size) {
    const float* x     = (const float*)d_in[0];
    const float* W1    = (const float*)d_in[1];
    const float* b1    = (const float*)d_in[2];
    const float* W2    = (const float*)d_in[3];
    const float* b2    = (const float*)d_in[4];
    const int*   ei    = (const int*)d_in[5];
    const int*   batch = (const int*)d_in[6];
    const int* row = ei;        // edge_index[0] = source
    const int* col = ei + NE;   // edge_index[1] = target

    float* out_hs = (float*)d_out;
    float* out_h  = (float*)d_out + (size_t)NG * HIDF;

    float *bufA, *bufB;
    cudaGetSymbolAddress((void**)&bufA, g_bufA);
    cudaGetSymbolAddress((void**)&bufB, g_bufB);
    __nv_bfloat16 *w1h, *w1l, *w2h, *w2l;
    cudaGetSymbolAddress((void**)&w1h, g_w1h);
    cudaGetSymbolAddress((void**)&w1l, g_w1l);
    cudaGetSymbolAddress((void**)&w2h, g_w2h);
    cudaGetSymbolAddress((void**)&w2l, g_w2l);

    // graph structure + weight prep
    k_init <<<(NN + 255) / 256, 256>>>();
    k_count<<<(NE + 255) / 256, 256>>>(col);
    k_scan <<<1, 1024>>>();
    k_fill <<<(NE + 255) / 256, 256>>>(row, col);
    k_prepw<<<(128 * 512 + 255) / 256, 256>>>(W1, W2);

    const int GEMM_GRID = (NN + 127) / 128;  // 391
    const int AGG_GRID  = (NN + 7) / 8;      // 6250

    // layer 1
    gemm_mma<<<GEMM_GRID, 256>>>(x, w1h, w1l, bufA, NN, INF_);
    k_agg<<<AGG_GRID, 256>>>(bufA, bufB, b1, 1);

    // layer 2
    gemm_mma<<<GEMM_GRID, 256>>>(bufB, w2h, w2l, bufA, NN, HIDF);
    k_agg<<<AGG_GRID, 256>>>(bufA, out_h, b2, 0);

    // pooling
    k_pool<<<NG, 128>>>(out_h, batch, out_hs);
}

// round 4
// speedup vs baseline: 1.4645x; 1.0807x over previous
#include <cuda_runtime.h>
#include <cuda_fp16.h>
#include <cstdint>
#include <cstddef>

#define NN   50000
#define NE   640000
#define INF_ 512
#define HIDF 128
#define NG   256

// ---------------- device scratch (no allocations allowed) ----------------
__device__ int   g_cnt[NN];
__device__ float g_dinv[NN];
__device__ int   g_rowptr[NN + 1];
__device__ int   g_cursor[NN];
__device__ int   g_src[NE];
__device__ float g_bufA[(size_t)NN * HIDF];   // gemm outputs
__device__ __half g_h1h[(size_t)NN * HIDF];   // layer-1 agg output, fp16 hi
__device__ __half g_h1l[(size_t)NN * HIDF];   // layer-1 agg output, fp16 lo
// transposed fp16 weights: Wt[n][k] = W[k][n]
__device__ __half g_w1h[128 * 512];
__device__ __half g_w2h[128 * 128];

// ---------------- helpers ----------------
__device__ __forceinline__ uint32_t smem_u32(const void* p) {
    uint32_t a;
    asm("{ .reg .u64 t; cvta.to.shared.u64 t, %1; cvt.u32.u64 %0, t; }" : "=r"(a) : "l"(p));
    return a;
}
__device__ __forceinline__ void ldsm_x4(uint32_t& r0, uint32_t& r1, uint32_t& r2, uint32_t& r3,
                                        uint32_t addr) {
    asm volatile("ldmatrix.sync.aligned.m8n8.x4.shared.b16 {%0,%1,%2,%3}, [%4];"
                 : "=r"(r0), "=r"(r1), "=r"(r2), "=r"(r3) : "r"(addr));
}
__device__ __forceinline__ void mma_f16(float* c, const uint32_t* a, const uint32_t* b) {
    asm volatile(
        "mma.sync.aligned.m16n8k16.row.col.f32.f16.f16.f32 "
        "{%0,%1,%2,%3}, {%4,%5,%6,%7}, {%8,%9}, {%0,%1,%2,%3};"
        : "+f"(c[0]), "+f"(c[1]), "+f"(c[2]), "+f"(c[3])
        : "r"(a[0]), "r"(a[1]), "r"(a[2]), "r"(a[3]), "r"(b[0]), "r"(b[1]));
}

// ---------------- graph preprocessing ----------------
__global__ void k_init() {
    int i = blockIdx.x * blockDim.x + threadIdx.x;
    if (i < NN) g_cnt[i] = 0;
}

// 4 edges per thread (int4) for MLP
__global__ void k_count(const int* __restrict__ col) {
    int t = blockIdx.x * blockDim.x + threadIdx.x;
    if (t < NE / 4) {
        int4 c4 = ((const int4*)col)[t];
        atomicAdd(&g_cnt[c4.x], 1);
        atomicAdd(&g_cnt[c4.y], 1);
        atomicAdd(&g_cnt[c4.z], 1);
        atomicAdd(&g_cnt[c4.w], 1);
    }
}

// 1024-thread single-block scan: segment-per-thread + 2-level warp scan
__global__ __launch_bounds__(1024) void k_scan() {
    __shared__ int wsum[32];
    const int SEG = (NN + 1023) / 1024;  // 49
    int t = threadIdx.x, lane = t & 31, w = t >> 5;
    int s0 = t * SEG, s1 = s0 + SEG;
    if (s1 > NN) s1 = NN;
    if (s0 > NN) s0 = NN;
    int s = 0;
    for (int i = s0; i < s1; i++) s += g_cnt[i];
    int v = s;
    #pragma unroll
    for (int o = 1; o < 32; o <<= 1) {
        int u = __shfl_up_sync(0xFFFFFFFFu, v, o);
        if (lane >= o) v += u;
    }
    if (lane == 31) wsum[w] = v;
    __syncthreads();
    if (w == 0) {
        int x = wsum[lane];
        #pragma unroll
        for (int o = 1; o < 32; o <<= 1) {
            int u = __shfl_up_sync(0xFFFFFFFFu, x, o);
            if (lane >= o) x += u;
        }
        wsum[lane] = x;
    }
    __syncthreads();
    int P = v - s + (w > 0 ? wsum[w - 1] : 0);
    for (int i = s0; i < s1; i++) {
        int c = g_cnt[i];
        g_rowptr[i] = P;
        g_cursor[i] = P;
        g_dinv[i] = rsqrtf((float)(c + 1));  // +1 self-loop
        P += c;
    }
    if (t == 1023) g_rowptr[NN] = wsum[31];
}

__global__ void k_fill(const int* __restrict__ row, const int* __restrict__ col) {
    int t = blockIdx.x * blockDim.x + threadIdx.x;
    if (t < NE / 4) {
        int4 r4 = ((const int4*)row)[t];
        int4 c4 = ((const int4*)col)[t];
        g_src[atomicAdd(&g_cursor[c4.x], 1)] = r4.x;
        g_src[atomicAdd(&g_cursor[c4.y], 1)] = r4.y;
        g_src[atomicAdd(&g_cursor[c4.z], 1)] = r4.z;
        g_src[atomicAdd(&g_cursor[c4.w], 1)] = r4.w;
    }
}

// transpose + fp16 cast of W1, W2
__global__ void k_prepw(const float* __restrict__ W1, const float* __restrict__ W2) {
    int i = blockIdx.x * blockDim.x + threadIdx.x;
    if (i < 128 * 512) {
        int n = i >> 9, k = i & 511;
        g_w1h[i] = __float2half_rn(W1[k * 128 + n]);
    }
    if (i < 128 * 128) {
        int n = i >> 7, k = i & 127;
        g_w2h[i] = __float2half_rn(W2[k * 128 + n]);
    }
}

// ---------------- HMMA GEMM: C[M,128] = A[M,K] @ Wt^T, 2-term fp16 split ----------------
// BM=128, BN=128, BK=32, 256 threads, warp tile 32x64.
// smem tiles padded to 80B rows -> conflict-free ldmatrix.
#define ASTRIDE 40  // fp16 elems per smem row (80 B)

struct GemmSmem {
    __half sAh[128 * ASTRIDE];
    __half sAl[128 * ASTRIDE];
    __half sBh[128 * ASTRIDE];
};

// F32A: A is fp32, converted in-kernel. F16A: A pre-split into (Ah, Al) fp16.
template <bool F32A>
__device__ __forceinline__ void gemm_body(const void* __restrict__ Aptr,
                                          const void* __restrict__ Aptr2,
                                          const __half* __restrict__ Bh,
                                          float* __restrict__ C,
                                          int M, int K) {
    __shared__ GemmSmem sm;
    const int tid = threadIdx.x;
    const int wid = tid >> 5, lane = tid & 31;
    const int wm = (wid >> 1) * 32;
    const int wn = (wid & 1) * 64;
    const int g = lane >> 2, tig = lane & 3;
    const int row0 = blockIdx.x * 128;

    const uint32_t uAh = smem_u32(sm.sAh), uAl = smem_u32(sm.sAl);
    const uint32_t uBh = smem_u32(sm.sBh);

    float c[2][8][4];
    #pragma unroll
    for (int mt = 0; mt < 2; mt++)
        #pragma unroll
        for (int nt = 0; nt < 8; nt++)
            #pragma unroll
            for (int q = 0; q < 4; q++) c[mt][nt][q] = 0.f;

    const int nch = K >> 5;

    float4 pa[4];        // F32A path
    uint4 pah[2], pal[2]; // F16A path
    uint4 pbh[2];

    // ---- load chunk 0 ----
    if (F32A) {
        const float* A = (const float*)Aptr;
        #pragma unroll
        for (int i = 0; i < 4; i++) {
            int q = i * 256 + tid;
            int r = q >> 3, c4 = q & 7;
            int gr = row0 + r;
            pa[i] = (gr < M) ? *(const float4*)(A + (size_t)gr * K + c4 * 4)
                             : make_float4(0.f, 0.f, 0.f, 0.f);
        }
    } else {
        const __half* Ah = (const __half*)Aptr;
        const __half* Al = (const __half*)Aptr2;
        #pragma unroll
        for (int i = 0; i < 2; i++) {
            int q = i * 256 + tid;
            int r = q >> 2, c16 = q & 3;
            int gr = row0 + r;
            if (gr < M) {
                pah[i] = *(const uint4*)(Ah + (size_t)gr * K + c16 * 8);
                pal[i] = *(const uint4*)(Al + (size_t)gr * K + c16 * 8);
            } else {
                pah[i] = make_uint4(0, 0, 0, 0);
                pal[i] = make_uint4(0, 0, 0, 0);
            }
        }
    }
    #pragma unroll
    for (int i = 0; i < 2; i++) {
        int q = i * 256 + tid;
        int r = q >> 2, c16 = q & 3;
        pbh[i] = *(const uint4*)(Bh + (size_t)r * K + c16 * 8);
    }

    for (int ch = 0; ch < nch; ch++) {
        // ---- store prefetched chunk to smem ----
        if (F32A) {
            #pragma unroll
            for (int i = 0; i < 4; i++) {
                int q = i * 256 + tid;
                int r = q >> 3, c4 = q & 7;
                float4 v = pa[i];
                __half hx = __float2half_rn(v.x), hy = __float2half_rn(v.y);
                __half hz = __float2half_rn(v.z), hw = __float2half_rn(v.w);
                __half2 h0 = __halves2half2(hx, hy), h1 = __halves2half2(hz, hw);
                __half2 l0 = __halves2half2(__float2half_rn(v.x - __half2float(hx)),
                                            __float2half_rn(v.y - __half2float(hy)));
                __half2 l1 = __halves2half2(__float2half_rn(v.z - __half2float(hz)),
                                            __float2half_rn(v.w - __half2float(hw)));
                int e = r * ASTRIDE + c4 * 4;
                *(uint32_t*)((char*)sm.sAh + e * 2)     = *(uint32_t*)&h0;
                *(uint32_t*)((char*)sm.sAh + e * 2 + 4) = *(uint32_t*)&h1;
                *(uint32_t*)((char*)sm.sAl + e * 2)     = *(uint32_t*)&l0;
                *(uint32_t*)((char*)sm.sAl + e * 2 + 4) = *(uint32_t*)&l1;
            }
        } else {
            #pragma unroll
            for (int i = 0; i < 2; i++) {
                int q = i * 256 + tid;
                int r = q >> 2, c16 = q & 3;
                int e = r * ASTRIDE + c16 * 8;
                *(uint4*)((char*)sm.sAh + e * 2) = pah[i];
                *(uint4*)((char*)sm.sAl + e * 2) = pal[i];
            }
        }
        #pragma unroll
        for (int i = 0; i < 2; i++) {
            int q = i * 256 + tid;
            int r = q >> 2, c16 = q & 3;
            int e = r * ASTRIDE + c16 * 8;
            *(uint4*)((char*)sm.sBh + e * 2) = pbh[i];
        }
        __syncthreads();

        // ---- issue global loads for next chunk ----
        if (ch + 1 < nch) {
            int k0 = (ch + 1) << 5;
            if (F32A) {
                const float* A = (const float*)Aptr;
                #pragma unroll
                for (int i = 0; i < 4; i++) {
                    int q = i * 256 + tid;
                    int r = q >> 3, c4 = q & 7;
                    int gr = row0 + r;
                    pa[i] = (gr < M) ? *(const float4*)(A + (size_t)gr * K + k0 + c4 * 4)
                                     : make_float4(0.f, 0.f, 0.f, 0.f);
                }
            } else {
                const __half* Ah = (const __half*)Aptr;
                const __half* Al = (const __half*)Aptr2;
                #pragma unroll
                for (int i = 0; i < 2; i++) {
                    int q = i * 256 + tid;
                    int r = q >> 2, c16 = q & 3;
                    int gr = row0 + r;
                    if (gr < M) {
                        pah[i] = *(const uint4*)(Ah + (size_t)gr * K + k0 + c16 * 8);
                        pal[i] = *(const uint4*)(Al + (size_t)gr * K + k0 + c16 * 8);
                    } else {
                        pah[i] = make_uint4(0, 0, 0, 0);
                        pal[i] = make_uint4(0, 0, 0, 0);
                    }
                }
            }
            #pragma unroll
            for (int i = 0; i < 2; i++) {
                int q = i * 256 + tid;
                int r = q >> 2, c16 = q & 3;
                pbh[i] = *(const uint4*)(Bh + (size_t)r * K + k0 + c16 * 8);
            }
        }

        // ---- compute: 2 ksteps of k16 ----
        #pragma unroll
        for (int ks = 0; ks < 2; ks++) {
            const int kc = ks * 16 + ((lane & 16) ? 8 : 0);
            uint32_t ah[2][4], al[2][4];
            #pragma unroll
            for (int mt = 0; mt < 2; mt++) {
                int r = wm + mt * 16 + (lane & 15);
                uint32_t off = (uint32_t)(r * ASTRIDE + kc) * 2;
                ldsm_x4(ah[mt][0], ah[mt][1], ah[mt][2], ah[mt][3], uAh + off);
                ldsm_x4(al[mt][0], al[mt][1], al[mt][2], al[mt][3], uAl + off);
            }
            uint32_t bh[8][2];
            const int kcb = ks * 16 + ((lane & 8) ? 8 : 0);
            #pragma unroll
            for (int nt4 = 0; nt4 < 4; nt4++) {
                int n = wn + nt4 * 16 + ((lane & 7) | ((lane & 16) ? 8 : 0));
                uint32_t off = (uint32_t)(n * ASTRIDE + kcb) * 2;
                ldsm_x4(bh[2 * nt4][0], bh[2 * nt4][1], bh[2 * nt4 + 1][0], bh[2 * nt4 + 1][1],
                        uBh + off);
            }
            #pragma unroll
            for (int mt = 0; mt < 2; mt++)
                #pragma unroll
                for (int nt = 0; nt < 8; nt++) {
                    mma_f16(c[mt][nt], ah[mt], bh[nt]);
                    mma_f16(c[mt][nt], al[mt], bh[nt]);
                }
        }
        __syncthreads();
    }

    // ---- epilogue ----
    #pragma unroll
    for (int mt = 0; mt < 2; mt++) {
        int gr0 = row0 + wm + mt * 16 + g;
        int gr1 = gr0 + 8;
        #pragma unroll
        for (int nt = 0; nt < 8; nt++) {
            int cc = wn + nt * 8 + 2 * tig;
            if (gr0 < M) *(float2*)(C + (size_t)gr0 * 128 + cc) = make_float2(c[mt][nt][0], c[mt][nt][1]);
            if (gr1 < M) *(float2*)(C + (size_t)gr1 * 128 + cc) = make_float2(c[mt][nt][2], c[mt][nt][3]);
        }
    }
}

__global__ __launch_bounds__(256) void gemm_f32A(const float* __restrict__ A,
                                                 const __half* __restrict__ Bh,
                                                 float* __restrict__ C, int M, int K) {
    gemm_body<true>(A, nullptr, Bh, C, M, K);
}
__global__ __launch_bounds__(256) void gemm_f16A(const __half* __restrict__ Ah,
                                                 const __half* __restrict__ Al,
                                                 const __half* __restrict__ Bh,
                                                 float* __restrict__ C, int M, int K) {
    gemm_body<false>(Ah, Al, Bh, C, M, K);
}

// ---------------- GCN aggregation: one warp per node, CSR gather ----------------
// Layer 1: relu, then emit fp16 hi/lo split (feeds gemm_f16A).
__global__ __launch_bounds__(256) void k_agg_f16(const float* __restrict__ in,
                                                 __half* __restrict__ outh,
                                                 __half* __restrict__ outl,
                                                 const float* __restrict__ bias) {
    int warp = (blockIdx.x * blockDim.x + threadIdx.x) >> 5;
    int lane = threadIdx.x & 31;
    if (warp >= NN) return;
    float dn = g_dinv[warp];
    float4 v = ((const float4*)(in + (size_t)warp * HIDF))[lane];
    float s = dn * dn;
    float4 acc = make_float4(v.x * s, v.y * s, v.z * s, v.w * s);
    int beg = g_rowptr[warp], end = g_rowptr[warp + 1];
    for (int j = beg; j < end; j++) {
        int src = g_src[j];
        float w = g_dinv[src] * dn;
        float4 u = ((const float4*)(in + (size_t)src * HIDF))[lane];
        acc.x += u.x * w; acc.y += u.y * w;
        acc.z += u.z * w; acc.w += u.w * w;
    }
    float4 b = ((const float4*)bias)[lane];
    acc.x = fmaxf(acc.x + b.x, 0.f); acc.y = fmaxf(acc.y + b.y, 0.f);
    acc.z = fmaxf(acc.z + b.z, 0.f); acc.w = fmaxf(acc.w + b.w, 0.f);
    __half hx = __float2half_rn(acc.x), hy = __float2half_rn(acc.y);
    __half hz = __float2half_rn(acc.z), hw = __float2half_rn(acc.w);
    __half2 h0 = __halves2half2(hx, hy), h1 = __halves2half2(hz, hw);
    __half2 l0 = __halves2half2(__float2half_rn(acc.x - __half2float(hx)),
                                __float2half_rn(acc.y - __half2float(hy)));
    __half2 l1 = __halves2half2(__float2half_rn(acc.z - __half2float(hz)),
                                __float2half_rn(acc.w - __half2float(hw)));
    uint2 ph = make_uint2(*(uint32_t*)&h0, *(uint32_t*)&h1);
    uint2 pl = make_uint2(*(uint32_t*)&l0, *(uint32_t*)&l1);
    ((uint2*)(outh + (size_t)warp * HIDF))[lane] = ph;
    ((uint2*)(outl + (size_t)warp * HIDF))[lane] = pl;
}

// Layer 2: fp32 out, no relu.
__global__ __launch_bounds__(256) void k_agg_f32(const float* __restrict__ in,
                                                 float* __restrict__ out,
                                                 const float* __restrict__ bias) {
    int warp = (blockIdx.x * blockDim.x + threadIdx.x) >> 5;
    int lane = threadIdx.x & 31;
    if (warp >= NN) return;
    float dn = g_dinv[warp];
    float4 v = ((const float4*)(in + (size_t)warp * HIDF))[lane];
    float s = dn * dn;
    float4 acc = make_float4(v.x * s, v.y * s, v.z * s, v.w * s);
    int beg = g_rowptr[warp], end = g_rowptr[warp + 1];
    for (int j = beg; j < end; j++) {
        int src = g_src[j];
        float w = g_dinv[src] * dn;
        float4 u = ((const float4*)(in + (size_t)src * HIDF))[lane];
        acc.x += u.x * w; acc.y += u.y * w;
        acc.z += u.z * w; acc.w += u.w * w;
    }
    float4 b = ((const float4*)bias)[lane];
    acc.x += b.x; acc.y += b.y; acc.z += b.z; acc.w += b.w;
    ((float4*)(out + (size_t)warp * HIDF))[lane] = acc;
}

// ---------------- global_add_pool: batch is sorted -> segmented sum ----------------
__global__ void k_pool(const float* __restrict__ h, const int* __restrict__ batch,
                       float* __restrict__ out) {
    int g = blockIdx.x;
    int t = threadIdx.x;
    int a = 0, b = NN;
    while (a < b) { int m = (a + b) >> 1; if (batch[m] < g) a = m + 1; else b = m; }
    int s = a;
    a = 0; b = NN;
    while (a < b) { int m = (a + b) >> 1; if (batch[m] < g + 1) a = m + 1; else b = m; }
    int e = a;
    float acc = 0.f;
    for (int n = s; n < e; n++) acc += h[(size_t)n * HIDF + t];
    out[(size_t)g * HIDF + t] = acc;
}

// ---------------- launch ----------------
extern "C" void kernel_launch(void* const* d_in, const int* in_sizes, int n_in,
                              void* d_out, int out_size) {
    const float* x     = (const float*)d_in[0];
    const float* W1    = (const float*)d_in[1];
    const float* b1    = (const float*)d_in[2];
    const float* W2    = (const float*)d_in[3];
    const float* b2    = (const float*)d_in[4];
    const int*   ei    = (const int*)d_in[5];
    const int*   batch = (const int*)d_in[6];
    const int* row = ei;        // edge_index[0] = source
    const int* col = ei + NE;   // edge_index[1] = target

    float* out_hs = (float*)d_out;
    float* out_h  = (float*)d_out + (size_t)NG * HIDF;

    float *bufA;
    __half *h1h, *h1l, *w1h, *w2h;
    cudaGetSymbolAddress((void**)&bufA, g_bufA);
    cudaGetSymbolAddress((void**)&h1h, g_h1h);
    cudaGetSymbolAddress((void**)&h1l, g_h1l);
    cudaGetSymbolAddress((void**)&w1h, g_w1h);
    cudaGetSymbolAddress((void**)&w2h, g_w2h);

    // graph structure + weight prep
    k_init <<<(NN + 255) / 256, 256>>>();
    k_count<<<(NE / 4 + 255) / 256, 256>>>(col);
    k_scan <<<1, 1024>>>();
    k_fill <<<(NE / 4 + 255) / 256, 256>>>(row, col);
    k_prepw<<<(128 * 512 + 255) / 256, 256>>>(W1, W2);

    const int GEMM_GRID = (NN + 127) / 128;  // 391
    const int AGG_GRID  = (NN + 7) / 8;      // 6250

    // layer 1
    gemm_f32A<<<GEMM_GRID, 256>>>(x, w1h, bufA, NN, INF_);
    k_agg_f16<<<AGG_GRID, 256>>>(bufA, h1h, h1l, b1);

    // layer 2
    gemm_f16A<<<GEMM_GRID, 256>>>(h1h, h1l, w2h, bufA, NN, HIDF);
    k_agg_f32<<<AGG_GRID, 256>>>(bufA, out_h, b2);

    // pooling
    k_pool<<<NG, 128>>>(out_h, batch, out_hs);
}

// round 5
// speedup vs baseline: 2.1490x; 1.4674x over previous
#include <cuda_runtime.h>
#include <cuda_fp16.h>
#include <cstdint>
#include <cstddef>

#define NN   50000
#define NE   640000
#define INF_ 512
#define HIDF 128
#define NG   256

// ---------------- device scratch (no allocations allowed) ----------------
__device__ int   g_cnt[NN];
__device__ float g_dinv[NN];
__device__ int   g_rowptr[NN + 1];
__device__ int   g_rank[NE];
__device__ int   g_src[NE];
__device__ __half g_g1[(size_t)NN * HIDF];    // gemm outputs (fp16), reused both layers
__device__ __half g_h1h[(size_t)NN * HIDF];   // layer-1 agg output, fp16 hi
__device__ __half g_h1l[(size_t)NN * HIDF];   // layer-1 agg output, fp16 lo
// transposed fp16 weights: Wt[n][k] = W[k][n]
__device__ __half g_w1h[128 * 512];
__device__ __half g_w2h[128 * 128];

// ---------------- helpers ----------------
__device__ __forceinline__ uint32_t smem_u32(const void* p) {
    uint32_t a;
    asm("{ .reg .u64 t; cvta.to.shared.u64 t, %1; cvt.u32.u64 %0, t; }" : "=r"(a) : "l"(p));
    return a;
}
__device__ __forceinline__ void ldsm_x4(uint32_t& r0, uint32_t& r1, uint32_t& r2, uint32_t& r3,
                                        uint32_t addr) {
    asm volatile("ldmatrix.sync.aligned.m8n8.x4.shared.b16 {%0,%1,%2,%3}, [%4];"
                 : "=r"(r0), "=r"(r1), "=r"(r2), "=r"(r3) : "r"(addr));
}
__device__ __forceinline__ void mma_f16(float* c, const uint32_t* a, const uint32_t* b) {
    asm volatile(
        "mma.sync.aligned.m16n8k16.row.col.f32.f16.f16.f32 "
        "{%0,%1,%2,%3}, {%4,%5,%6,%7}, {%8,%9}, {%0,%1,%2,%3};"
        : "+f"(c[0]), "+f"(c[1]), "+f"(c[2]), "+f"(c[3])
        : "r"(a[0]), "r"(a[1]), "r"(a[2]), "r"(a[3]), "r"(b[0]), "r"(b[1]));
}

// ---------------- preprocessing ----------------
// merged: zero counts + transpose/cast weights. grid covers 65536 threads.
__global__ void k_initprep(const float* __restrict__ W1, const float* __restrict__ W2) {
    int i = blockIdx.x * blockDim.x + threadIdx.x;
    if (i < NN) g_cnt[i] = 0;
    if (i < 128 * 512) {
        int n = i >> 9, k = i & 511;
        g_w1h[i] = __float2half_rn(W1[k * 128 + n]);
    }
    if (i < 128 * 128) {
        int n = i >> 7, k = i & 127;
        g_w2h[i] = __float2half_rn(W2[k * 128 + n]);
    }
}

// count + record per-edge rank within destination (atomicAdd return value)
__global__ void k_count(const int* __restrict__ col) {
    int t = blockIdx.x * blockDim.x + threadIdx.x;
    if (t < NE / 4) {
        int4 c4 = ((const int4*)col)[t];
        int4 r;
        r.x = atomicAdd(&g_cnt[c4.x], 1);
        r.y = atomicAdd(&g_cnt[c4.y], 1);
        r.z = atomicAdd(&g_cnt[c4.z], 1);
        r.w = atomicAdd(&g_cnt[c4.w], 1);
        ((int4*)g_rank)[t] = r;
    }
}

// single-block scan, smem-staged for fully coalesced global access
__global__ __launch_bounds__(1024) void k_scan() {
    extern __shared__ int sc[];   // NN ints = 200 000 B
    __shared__ int wsum[32];
    int t = threadIdx.x, lane = t & 31, w = t >> 5;
    // coalesced load of counts; dinv computed on the way
    for (int i = t; i < NN; i += 1024) {
        int c = g_cnt[i];
        sc[i] = c;
        g_dinv[i] = rsqrtf((float)(c + 1));  // +1 self-loop
    }
    __syncthreads();
    const int SEG = (NN + 1023) / 1024;  // 49
    int s0 = t * SEG, s1 = s0 + SEG;
    if (s1 > NN) s1 = NN;
    if (s0 > NN) s0 = NN;
    int s = 0;
    for (int i = s0; i < s1; i++) s += sc[i];
    int v = s;
    #pragma unroll
    for (int o = 1; o < 32; o <<= 1) {
        int u = __shfl_up_sync(0xFFFFFFFFu, v, o);
        if (lane >= o) v += u;
    }
    if (lane == 31) wsum[w] = v;
    __syncthreads();
    if (w == 0) {
        int x = wsum[lane];
        #pragma unroll
        for (int o = 1; o < 32; o <<= 1) {
            int u = __shfl_up_sync(0xFFFFFFFFu, x, o);
            if (lane >= o) x += u;
        }
        wsum[lane] = x;
    }
    __syncthreads();
    int P = v - s + (w > 0 ? wsum[w - 1] : 0);
    for (int i = s0; i < s1; i++) {
        int c = sc[i];
        sc[i] = P;     // in-place exclusive prefix
        P += c;
    }
    __syncthreads();
    // coalesced writeback
    for (int i = t; i < NN; i += 1024) g_rowptr[i] = sc[i];
    if (t == 0) g_rowptr[NN] = wsum[31];
}

// atomic-free fill using precomputed ranks
__global__ void k_fill(const int* __restrict__ row, const int* __restrict__ col) {
    int t = blockIdx.x * blockDim.x + threadIdx.x;
    if (t < NE / 4) {
        int4 r4 = ((const int4*)row)[t];
        int4 c4 = ((const int4*)col)[t];
        int4 k4 = ((const int4*)g_rank)[t];
        g_src[g_rowptr[c4.x] + k4.x] = r4.x;
        g_src[g_rowptr[c4.y] + k4.y] = r4.y;
        g_src[g_rowptr[c4.z] + k4.z] = r4.z;
        g_src[g_rowptr[c4.w] + k4.w] = r4.w;
    }
}

// ---------------- HMMA GEMM: C[M,128] = A[M,K] @ Wt^T, 2-term fp16 split, fp16 out ----------------
#define ASTRIDE 40  // fp16 elems per smem row (80 B), conflict-free ldmatrix

struct GemmSmem {
    __half sAh[128 * ASTRIDE];
    __half sAl[128 * ASTRIDE];
    __half sBh[128 * ASTRIDE];
};

template <bool F32A>
__device__ __forceinline__ void gemm_body(const void* __restrict__ Aptr,
                                          const void* __restrict__ Aptr2,
                                          const __half* __restrict__ Bh,
                                          __half* __restrict__ C,
                                          int M, int K) {
    __shared__ GemmSmem sm;
    const int tid = threadIdx.x;
    const int wid = tid >> 5, lane = tid & 31;
    const int wm = (wid >> 1) * 32;
    const int wn = (wid & 1) * 64;
    const int g = lane >> 2, tig = lane & 3;
    const int row0 = blockIdx.x * 128;

    const uint32_t uAh = smem_u32(sm.sAh), uAl = smem_u32(sm.sAl);
    const uint32_t uBh = smem_u32(sm.sBh);

    float c[2][8][4];
    #pragma unroll
    for (int mt = 0; mt < 2; mt++)
        #pragma unroll
        for (int nt = 0; nt < 8; nt++)
            #pragma unroll
            for (int q = 0; q < 4; q++) c[mt][nt][q] = 0.f;

    const int nch = K >> 5;

    float4 pa[4];
    uint4 pah[2], pal[2];
    uint4 pbh[2];

    // ---- load chunk 0 ----
    if (F32A) {
        const float* A = (const float*)Aptr;
        #pragma unroll
        for (int i = 0; i < 4; i++) {
            int q = i * 256 + tid;
            int r = q >> 3, c4 = q & 7;
            int gr = row0 + r;
            pa[i] = (gr < M) ? *(const float4*)(A + (size_t)gr * K + c4 * 4)
                             : make_float4(0.f, 0.f, 0.f, 0.f);
        }
    } else {
        const __half* Ah = (const __half*)Aptr;
        const __half* Al = (const __half*)Aptr2;
        #pragma unroll
        for (int i = 0; i < 2; i++) {
            int q = i * 256 + tid;
            int r = q >> 2, c16 = q & 3;
            int gr = row0 + r;
            if (gr < M) {
                pah[i] = *(const uint4*)(Ah + (size_t)gr * K + c16 * 8);
                pal[i] = *(const uint4*)(Al + (size_t)gr * K + c16 * 8);
            } else {
                pah[i] = make_uint4(0, 0, 0, 0);
                pal[i] = make_uint4(0, 0, 0, 0);
            }
        }
    }
    #pragma unroll
    for (int i = 0; i < 2; i++) {
        int q = i * 256 + tid;
        int r = q >> 2, c16 = q & 3;
        pbh[i] = *(const uint4*)(Bh + (size_t)r * K + c16 * 8);
    }

    for (int ch = 0; ch < nch; ch++) {
        if (F32A) {
            #pragma unroll
            for (int i = 0; i < 4; i++) {
                int q = i * 256 + tid;
                int r = q >> 3, c4 = q & 7;
                float4 v = pa[i];
                __half hx = __float2half_rn(v.x), hy = __float2half_rn(v.y);
                __half hz = __float2half_rn(v.z), hw = __float2half_rn(v.w);
                __half2 h0 = __halves2half2(hx, hy), h1 = __halves2half2(hz, hw);
                __half2 l0 = __halves2half2(__float2half_rn(v.x - __half2float(hx)),
                                            __float2half_rn(v.y - __half2float(hy)));
                __half2 l1 = __halves2half2(__float2half_rn(v.z - __half2float(hz)),
                                            __float2half_rn(v.w - __half2float(hw)));
                int e = r * ASTRIDE + c4 * 4;
                *(uint32_t*)((char*)sm.sAh + e * 2)     = *(uint32_t*)&h0;
                *(uint32_t*)((char*)sm.sAh + e * 2 + 4) = *(uint32_t*)&h1;
                *(uint32_t*)((char*)sm.sAl + e * 2)     = *(uint32_t*)&l0;
                *(uint32_t*)((char*)sm.sAl + e * 2 + 4) = *(uint32_t*)&l1;
            }
        } else {
            #pragma unroll
            for (int i = 0; i < 2; i++) {
                int q = i * 256 + tid;
                int r = q >> 2, c16 = q & 3;
                int e = r * ASTRIDE + c16 * 8;
                *(uint4*)((char*)sm.sAh + e * 2) = pah[i];
                *(uint4*)((char*)sm.sAl + e * 2) = pal[i];
            }
        }
        #pragma unroll
        for (int i = 0; i < 2; i++) {
            int q = i * 256 + tid;
            int r = q >> 2, c16 = q & 3;
            int e = r * ASTRIDE + c16 * 8;
            *(uint4*)((char*)sm.sBh + e * 2) = pbh[i];
        }
        __syncthreads();

        if (ch + 1 < nch) {
            int k0 = (ch + 1) << 5;
            if (F32A) {
                const float* A = (const float*)Aptr;
                #pragma unroll
                for (int i = 0; i < 4; i++) {
                    int q = i * 256 + tid;
                    int r = q >> 3, c4 = q & 7;
                    int gr = row0 + r;
                    pa[i] = (gr < M) ? *(const float4*)(A + (size_t)gr * K + k0 + c4 * 4)
                                     : make_float4(0.f, 0.f, 0.f, 0.f);
                }
            } else {
                const __half* Ah = (const __half*)Aptr;
                const __half* Al = (const __half*)Aptr2;
                #pragma unroll
                for (int i = 0; i < 2; i++) {
                    int q = i * 256 + tid;
                    int r = q >> 2, c16 = q & 3;
                    int gr = row0 + r;
                    if (gr < M) {
                        pah[i] = *(const uint4*)(Ah + (size_t)gr * K + k0 + c16 * 8);
                        pal[i] = *(const uint4*)(Al + (size_t)gr * K + k0 + c16 * 8);
                    } else {
                        pah[i] = make_uint4(0, 0, 0, 0);
                        pal[i] = make_uint4(0, 0, 0, 0);
                    }
                }
            }
            #pragma unroll
            for (int i = 0; i < 2; i++) {
                int q = i * 256 + tid;
                int r = q >> 2, c16 = q & 3;
                pbh[i] = *(const uint4*)(Bh + (size_t)r * K + k0 + c16 * 8);
            }
        }

        #pragma unroll
        for (int ks = 0; ks < 2; ks++) {
            const int kc = ks * 16 + ((lane & 16) ? 8 : 0);
            uint32_t ah[2][4], al[2][4];
            #pragma unroll
            for (int mt = 0; mt < 2; mt++) {
                int r = wm + mt * 16 + (lane & 15);
                uint32_t off = (uint32_t)(r * ASTRIDE + kc) * 2;
                ldsm_x4(ah[mt][0], ah[mt][1], ah[mt][2], ah[mt][3], uAh + off);
                ldsm_x4(al[mt][0], al[mt][1], al[mt][2], al[mt][3], uAl + off);
            }
            uint32_t bh[8][2];
            const int kcb = ks * 16 + ((lane & 8) ? 8 : 0);
            #pragma unroll
            for (int nt4 = 0; nt4 < 4; nt4++) {
                int n = wn + nt4 * 16 + ((lane & 7) | ((lane & 16) ? 8 : 0));
                uint32_t off = (uint32_t)(n * ASTRIDE + kcb) * 2;
                ldsm_x4(bh[2 * nt4][0], bh[2 * nt4][1], bh[2 * nt4 + 1][0], bh[2 * nt4 + 1][1],
                        uBh + off);
            }
            #pragma unroll
            for (int mt = 0; mt < 2; mt++)
                #pragma unroll
                for (int nt = 0; nt < 8; nt++) {
                    mma_f16(c[mt][nt], ah[mt], bh[nt]);
                    mma_f16(c[mt][nt], al[mt], bh[nt]);
                }
        }
        __syncthreads();
    }

    // ---- epilogue: fp16 out ----
    #pragma unroll
    for (int mt = 0; mt < 2; mt++) {
        int gr0 = row0 + wm + mt * 16 + g;
        int gr1 = gr0 + 8;
        #pragma unroll
        for (int nt = 0; nt < 8; nt++) {
            int cc = wn + nt * 8 + 2 * tig;
            if (gr0 < M) *(__half2*)(C + (size_t)gr0 * 128 + cc) = __floats2half2_rn(c[mt][nt][0], c[mt][nt][1]);
            if (gr1 < M) *(__half2*)(C + (size_t)gr1 * 128 + cc) = __floats2half2_rn(c[mt][nt][2], c[mt][nt][3]);
        }
    }
}

__global__ __launch_bounds__(256) void gemm_f32A(const float* __restrict__ A,
                                                 const __half* __restrict__ Bh,
                                                 __half* __restrict__ C, int M, int K) {
    gemm_body<true>(A, nullptr, Bh, C, M, K);
}
__global__ __launch_bounds__(256) void gemm_f16A(const __half* __restrict__ Ah,
                                                 const __half* __restrict__ Al,
                                                 const __half* __restrict__ Bh,
                                                 __half* __restrict__ C, int M, int K) {
    gemm_body<false>(Ah, Al, Bh, C, M, K);
}

// ---------------- aggregation: one warp per node, CSR gather of fp16 rows ----------------
__device__ __forceinline__ float4 load_row4(const __half* __restrict__ in, int node, int lane) {
    uint2 pv = ((const uint2*)(in + (size_t)node * HIDF))[lane];  // 4 halves
    float2 fa = __half22float2(*(__half2*)&pv.x);
    float2 fb = __half22float2(*(__half2*)&pv.y);
    return make_float4(fa.x, fa.y, fb.x, fb.y);
}

// Layer 1: relu, emit fp16 hi/lo split (feeds gemm_f16A)
__global__ __launch_bounds__(256) void k_agg_f16(const __half* __restrict__ in,
                                                 __half* __restrict__ outh,
                                                 __half* __restrict__ outl,
                                                 const float* __restrict__ bias) {
    int warp = (blockIdx.x * blockDim.x + threadIdx.x) >> 5;
    int lane = threadIdx.x & 31;
    if (warp >= NN) return;
    float dn = g_dinv[warp];
    float4 v = load_row4(in, warp, lane);
    float s = dn * dn;
    float4 acc = make_float4(v.x * s, v.y * s, v.z * s, v.w * s);
    int beg = g_rowptr[warp], end = g_rowptr[warp + 1];
    for (int j = beg; j < end; j++) {
        int src = g_src[j];
        float w = g_dinv[src] * dn;
        float4 u = load_row4(in, src, lane);
        acc.x += u.x * w; acc.y += u.y * w;
        acc.z += u.z * w; acc.w += u.w * w;
    }
    float4 b = ((const float4*)bias)[lane];
    acc.x = fmaxf(acc.x + b.x, 0.f); acc.y = fmaxf(acc.y + b.y, 0.f);
    acc.z = fmaxf(acc.z + b.z, 0.f); acc.w = fmaxf(acc.w + b.w, 0.f);
    __half hx = __float2half_rn(acc.x), hy = __float2half_rn(acc.y);
    __half hz = __float2half_rn(acc.z), hw = __float2half_rn(acc.w);
    __half2 h0 = __halves2half2(hx, hy), h1 = __halves2half2(hz, hw);
    __half2 l0 = __halves2half2(__float2half_rn(acc.x - __half2float(hx)),
                                __float2half_rn(acc.y - __half2float(hy)));
    __half2 l1 = __halves2half2(__float2half_rn(acc.z - __half2float(hz)),
                                __float2half_rn(acc.w - __half2float(hw)));
    uint2 ph = make_uint2(*(uint32_t*)&h0, *(uint32_t*)&h1);
    uint2 pl = make_uint2(*(uint32_t*)&l0, *(uint32_t*)&l1);
    ((uint2*)(outh + (size_t)warp * HIDF))[lane] = ph;
    ((uint2*)(outl + (size_t)warp * HIDF))[lane] = pl;
}

// Layer 2: fp32 out (final h), no relu
__global__ __launch_bounds__(256) void k_agg_f32(const __half* __restrict__ in,
                                                 float* __restrict__ out,
                                                 const float* __restrict__ bias) {
    int warp = (blockIdx.x * blockDim.x + threadIdx.x) >> 5;
    int lane = threadIdx.x & 31;
    if (warp >= NN) return;
    float dn = g_dinv[warp];
    float4 v = load_row4(in, warp, lane);
    float s = dn * dn;
    float4 acc = make_float4(v.x * s, v.y * s, v.z * s, v.w * s);
    int beg = g_rowptr[warp], end = g_rowptr[warp + 1];
    for (int j = beg; j < end; j++) {
        int src = g_src[j];
        float w = g_dinv[src] * dn;
        float4 u = load_row4(in, src, lane);
        acc.x += u.x * w; acc.y += u.y * w;
        acc.z += u.z * w; acc.w += u.w * w;
    }
    float4 b = ((const float4*)bias)[lane];
    acc.x += b.x; acc.y += b.y; acc.z += b.z; acc.w += b.w;
    ((float4*)(out + (size_t)warp * HIDF))[lane] = acc;
}

// ---------------- global_add_pool: batch is sorted -> segmented sum ----------------
__global__ void k_pool(const float* __restrict__ h, const int* __restrict__ batch,
                       float* __restrict__ out) {
    int g = blockIdx.x;
    int t = threadIdx.x;
    int a = 0, b = NN;
    while (a < b) { int m = (a + b) >> 1; if (batch[m] < g) a = m + 1; else b = m; }
    int s = a;
    a = 0; b = NN;
    while (a < b) { int m = (a + b) >> 1; if (batch[m] < g + 1) a = m + 1; else b = m; }
    int e = a;
    float acc = 0.f;
    for (int n = s; n < e; n++) acc += h[(size_t)n * HIDF + t];
    out[(size_t)g * HIDF + t] = acc;
}

// ---------------- launch ----------------
extern "C" void kernel_launch(void* const* d_in, const int* in_sizes, int n_in,
                              void* d_out, int out_size) {
    const float* x     = (const float*)d_in[0];
    const float* W1    = (const float*)d_in[1];
    const float* b1    = (const float*)d_in[2];
    const float* W2    = (const float*)d_in[3];
    const float* b2    = (const float*)d_in[4];
    const int*   ei    = (const int*)d_in[5];
    const int*   batch = (const int*)d_in[6];
    const int* row = ei;        // edge_index[0] = source
    const int* col = ei + NE;   // edge_index[1] = target

    float* out_hs = (float*)d_out;
    float* out_h  = (float*)d_out + (size_t)NG * HIDF;

    __half *g1, *h1h, *h1l, *w1h, *w2h;
    cudaGetSymbolAddress((void**)&g1, g_g1);
    cudaGetSymbolAddress((void**)&h1h, g_h1h);
    cudaGetSymbolAddress((void**)&h1l, g_h1l);
    cudaGetSymbolAddress((void**)&w1h, g_w1h);
    cudaGetSymbolAddress((void**)&w2h, g_w2h);

    static bool configured = false;
    if (!configured) {
        cudaFuncSetAttribute(k_scan, cudaFuncAttributeMaxDynamicSharedMemorySize, NN * 4);
        configured = true;
    }

    // preprocessing
    k_initprep<<<256, 256>>>(W1, W2);                 // covers 65536 threads
    k_count<<<(NE / 4 + 255) / 256, 256>>>(col);
    k_scan<<<1, 1024, NN * 4>>>();
    k_fill<<<(NE / 4 + 255) / 256, 256>>>(row, col);

    const int GEMM_GRID = (NN + 127) / 128;  // 391
    const int AGG_GRID  = (NN + 7) / 8;      // 6250

    // layer 1
    gemm_f32A<<<GEMM_GRID, 256>>>(x, w1h, g1, NN, INF_);
    k_agg_f16<<<AGG_GRID, 256>>>(g1, h1h, h1l, b1);

    // layer 2
    gemm_f16A<<<GEMM_GRID, 256>>>(h1h, h1l, w2h, g1, NN, HIDF);
    k_agg_f32<<<AGG_GRID, 256>>>(g1, out_h, b2);

    // pooling
    k_pool<<<NG, 128>>>(out_h, batch, out_hs);
}

// round 9
// speedup vs baseline: 2.3396x; 1.0887x over previous
#include <cuda_runtime.h>
#include <cuda_fp16.h>
#include <cstdint>
#include <cstddef>

#define NN   50000
#define NE   640000
#define INF_ 512
#define HIDF 128
#define NG   256

// ---------------- device scratch (no allocations allowed) ----------------
__device__ int   g_cnt[NN];          // zero at load; k_scan restores to zero each launch
__device__ float g_dinv[NN];
__device__ int   g_rowptr[NN + 1];
__device__ int   g_rank[NE];
__device__ int   g_src[NE];
__device__ __half g_g1[(size_t)NN * HIDF];    // gemm outputs (fp16), reused both layers
__device__ __half g_h1h[(size_t)NN * HIDF];   // layer-1 agg output, fp16 hi
__device__ __half g_h1l[(size_t)NN * HIDF];   // layer-1 agg output, fp16 lo
// transposed fp16 weights: Wt[n][k] = W[k][n]
__device__ __half g_w1h[128 * 512];
__device__ __half g_w2h[128 * 128];

// ---------------- helpers ----------------
__device__ __forceinline__ uint32_t smem_u32(const void* p) {
    uint32_t a;
    asm("{ .reg .u64 t; cvta.to.shared.u64 t, %1; cvt.u32.u64 %0, t; }" : "=r"(a) : "l"(p));
    return a;
}
__device__ __forceinline__ void ldsm_x4(uint32_t& r0, uint32_t& r1, uint32_t& r2, uint32_t& r3,
                                        uint32_t addr) {
    asm volatile("ldmatrix.sync.aligned.m8n8.x4.shared.b16 {%0,%1,%2,%3}, [%4];"
                 : "=r"(r0), "=r"(r1), "=r"(r2), "=r"(r3) : "r"(addr));
}
__device__ __forceinline__ void mma_f16(float* c, const uint32_t* a, const uint32_t* b) {
    asm volatile(
        "mma.sync.aligned.m16n8k16.row.col.f32.f16.f16.f32 "
        "{%0,%1,%2,%3}, {%4,%5,%6,%7}, {%8,%9}, {%0,%1,%2,%3};"
        : "+f"(c[0]), "+f"(c[1]), "+f"(c[2]), "+f"(c[3])
        : "r"(a[0]), "r"(a[1]), "r"(a[2]), "r"(a[3]), "r"(b[0]), "r"(b[1]));
}

// ---------------- preprocessing ----------------
// transpose/cast weights (g_cnt zeroing handled by k_scan's restore)
__global__ void k_prepw(const float* __restrict__ W1, const float* __restrict__ W2) {
    int i = blockIdx.x * blockDim.x + threadIdx.x;
    if (i < 128 * 512) {
        int n = i >> 9, k = i & 511;
        g_w1h[i] = __float2half_rn(W1[k * 128 + n]);
    }
    if (i < 128 * 128) {
        int n = i >> 7, k = i & 127;
        g_w2h[i] = __float2half_rn(W2[k * 128 + n]);
    }
}

// count + record per-edge rank within destination (atomicAdd return value), 2 edges/thread
__global__ void k_count(const int* __restrict__ col) {
    int t = blockIdx.x * blockDim.x + threadIdx.x;
    if (t < NE / 2) {
        int2 c2 = ((const int2*)col)[t];
        int2 r;
        r.x = atomicAdd(&g_cnt[c2.x], 1);
        r.y = atomicAdd(&g_cnt[c2.y], 1);
        ((int2*)g_rank)[t] = r;
    }
}

// single-block scan, smem-staged for fully coalesced global access.
// Also restores g_cnt to zero for the next launch (invariant: zero at entry).
__global__ __launch_bounds__(1024) void k_scan() {
    extern __shared__ int sc[];   // NN ints = 200 000 B
    __shared__ int wsum[32];
    int t = threadIdx.x, lane = t & 31, w = t >> 5;
    for (int i = t; i < NN; i += 1024) {
        int c = g_cnt[i];
        sc[i] = c;
        g_dinv[i] = rsqrtf((float)(c + 1));  // +1 self-loop
        g_cnt[i] = 0;                        // restore invariant for next launch
    }
    __syncthreads();
    const int SEG = (NN + 1023) / 1024;  // 49
    int s0 = t * SEG, s1 = s0 + SEG;
    if (s1 > NN) s1 = NN;
    if (s0 > NN) s0 = NN;
    int s = 0;
    for (int i = s0; i < s1; i++) s += sc[i];
    int v = s;
    #pragma unroll
    for (int o = 1; o < 32; o <<= 1) {
        int u = __shfl_up_sync(0xFFFFFFFFu, v, o);
        if (lane >= o) v += u;
    }
    if (lane == 31) wsum[w] = v;
    __syncthreads();
    if (w == 0) {
        int x = wsum[lane];
        #pragma unroll
        for (int o = 1; o < 32; o <<= 1) {
            int u = __shfl_up_sync(0xFFFFFFFFu, x, o);
            if (lane >= o) x += u;
        }
        wsum[lane] = x;
    }
    __syncthreads();
    int P = v - s + (w > 0 ? wsum[w - 1] : 0);
    for (int i = s0; i < s1; i++) {
        int c = sc[i];
        sc[i] = P;     // in-place exclusive prefix
        P += c;
    }
    __syncthreads();
    for (int i = t; i < NN; i += 1024) g_rowptr[i] = sc[i];
    if (t == 0) g_rowptr[NN] = wsum[31];
}

// atomic-free fill using precomputed ranks, 2 edges/thread
__global__ void k_fill(const int* __restrict__ row, const int* __restrict__ col) {
    int t = blockIdx.x * blockDim.x + threadIdx.x;
    if (t < NE / 2) {
        int2 r2 = ((const int2*)row)[t];
        int2 c2 = ((const int2*)col)[t];
        int2 k2 = ((const int2*)g_rank)[t];
        g_src[g_rowptr[c2.x] + k2.x] = r2.x;
        g_src[g_rowptr[c2.y] + k2.y] = r2.y;
    }
}

// ---------------- HMMA GEMM: C[M,128] = A[M,K] @ Wt^T, fp16 out ----------------
// F32A+1-term: A fp32 -> fp16 (layer 1). F16A+2-term: A pre-split hi/lo (layer 2).
#define ASTRIDE 40  // fp16 elems per smem row (80 B), conflict-free ldmatrix

template <bool F32A, bool TWO>
__device__ __forceinline__ void gemm_body(const void* __restrict__ Aptr,
                                          const void* __restrict__ Aptr2,
                                          const __half* __restrict__ Bh,
                                          __half* __restrict__ C,
                                          int M, int K) {
    __shared__ __half sAh[128 * ASTRIDE];
    __shared__ __half sAl[TWO ? 128 * ASTRIDE : 8];
    __shared__ __half sBh[128 * ASTRIDE];
    const int tid = threadIdx.x;
    const int wid = tid >> 5, lane = tid & 31;
    const int wm = (wid >> 1) * 32;
    const int wn = (wid & 1) * 64;
    const int g = lane >> 2, tig = lane & 3;
    const int row0 = blockIdx.x * 128;

    const uint32_t uAh = smem_u32(sAh), uAl = smem_u32(sAl);
    const uint32_t uBh = smem_u32(sBh);

    float c[2][8][4];
    #pragma unroll
    for (int mt = 0; mt < 2; mt++)
        #pragma unroll
        for (int nt = 0; nt < 8; nt++)
            #pragma unroll
            for (int q = 0; q < 4; q++) c[mt][nt][q] = 0.f;

    const int nch = K >> 5;

    float4 pa[4];
    uint4 pah[2], pal[2];
    uint4 pbh[2];

    // ---- load chunk 0 ----
    if (F32A) {
        const float* A = (const float*)Aptr;
        #pragma unroll
        for (int i = 0; i < 4; i++) {
            int q = i * 256 + tid;
            int r = q >> 3, c4 = q & 7;
            int gr = row0 + r;
            pa[i] = (gr < M) ? *(const float4*)(A + (size_t)gr * K + c4 * 4)
                             : make_float4(0.f, 0.f, 0.f, 0.f);
        }
    } else {
        const __half* Ah = (const __half*)Aptr;
        const __half* Al = (const __half*)Aptr2;
        #pragma unroll
        for (int i = 0; i < 2; i++) {
            int q = i * 256 + tid;
            int r = q >> 2, c16 = q & 3;
            int gr = row0 + r;
            if (gr < M) {
                pah[i] = *(const uint4*)(Ah + (size_t)gr * K + c16 * 8);
                if (TWO) pal[i] = *(const uint4*)(Al + (size_t)gr * K + c16 * 8);
            } else {
                pah[i] = make_uint4(0, 0, 0, 0);
                if (TWO) pal[i] = make_uint4(0, 0, 0, 0);
            }
        }
    }
    #pragma unroll
    for (int i = 0; i < 2; i++) {
        int q = i * 256 + tid;
        int r = q >> 2, c16 = q & 3;
        pbh[i] = *(const uint4*)(Bh + (size_t)r * K + c16 * 8);
    }

    for (int ch = 0; ch < nch; ch++) {
        if (F32A) {
            #pragma unroll
            for (int i = 0; i < 4; i++) {
                int q = i * 256 + tid;
                int r = q >> 3, c4 = q & 7;
                float4 v = pa[i];
                __half2 h0 = __floats2half2_rn(v.x, v.y);
                __half2 h1 = __floats2half2_rn(v.z, v.w);
                int e = r * ASTRIDE + c4 * 4;
                *(uint32_t*)((char*)sAh + e * 2)     = *(uint32_t*)&h0;
                *(uint32_t*)((char*)sAh + e * 2 + 4) = *(uint32_t*)&h1;
            }
        } else {
            #pragma unroll
            for (int i = 0; i < 2; i++) {
                int q = i * 256 + tid;
                int r = q >> 2, c16 = q & 3;
                int e = r * ASTRIDE + c16 * 8;
                *(uint4*)((char*)sAh + e * 2) = pah[i];
                if (TWO) *(uint4*)((char*)sAl + e * 2) = pal[i];
            }
        }
        #pragma unroll
        for (int i = 0; i < 2; i++) {
            int q = i * 256 + tid;
            int r = q >> 2, c16 = q & 3;
            int e = r * ASTRIDE + c16 * 8;
            *(uint4*)((char*)sBh + e * 2) = pbh[i];
        }
        __syncthreads();

        if (ch + 1 < nch) {
            int k0 = (ch + 1) << 5;
            if (F32A) {
                const float* A = (const float*)Aptr;
                #pragma unroll
                for (int i = 0; i < 4; i++) {
                    int q = i * 256 + tid;
                    int r = q >> 3, c4 = q & 7;
                    int gr = row0 + r;
                    pa[i] = (gr < M) ? *(const float4*)(A + (size_t)gr * K + k0 + c4 * 4)
                                     : make_float4(0.f, 0.f, 0.f, 0.f);
                }
            } else {
                const __half* Ah = (const __half*)Aptr;
                const __half* Al = (const __half*)Aptr2;
                #pragma unroll
                for (int i = 0; i < 2; i++) {
                    int q = i * 256 + tid;
                    int r = q >> 2, c16 = q & 3;
                    int gr = row0 + r;
                    if (gr < M) {
                        pah[i] = *(const uint4*)(Ah + (size_t)gr * K + k0 + c16 * 8);
                        if (TWO) pal[i] = *(const uint4*)(Al + (size_t)gr * K + k0 + c16 * 8);
                    } else {
                        pah[i] = make_uint4(0, 0, 0, 0);
                        if (TWO) pal[i] = make_uint4(0, 0, 0, 0);
                    }
                }
            }
            #pragma unroll
            for (int i = 0; i < 2; i++) {
                int q = i * 256 + tid;
                int r = q >> 2, c16 = q & 3;
                pbh[i] = *(const uint4*)(Bh + (size_t)r * K + k0 + c16 * 8);
            }
        }

        #pragma unroll
        for (int ks = 0; ks < 2; ks++) {
            const int kc = ks * 16 + ((lane & 16) ? 8 : 0);
            uint32_t ah[2][4], al[2][4];
            #pragma unroll
            for (int mt = 0; mt < 2; mt++) {
                int r = wm + mt * 16 + (lane & 15);
                uint32_t off = (uint32_t)(r * ASTRIDE + kc) * 2;
                ldsm_x4(ah[mt][0], ah[mt][1], ah[mt][2], ah[mt][3], uAh + off);
                if (TWO) ldsm_x4(al[mt][0], al[mt][1], al[mt][2], al[mt][3], uAl + off);
            }
            uint32_t bh[8][2];
            const int kcb = ks * 16 + ((lane & 8) ? 8 : 0);
            #pragma unroll
            for (int nt4 = 0; nt4 < 4; nt4++) {
                int n = wn + nt4 * 16 + ((lane & 7) | ((lane & 16) ? 8 : 0));
                uint32_t off = (uint32_t)(n * ASTRIDE + kcb) * 2;
                ldsm_x4(bh[2 * nt4][0], bh[2 * nt4][1], bh[2 * nt4 + 1][0], bh[2 * nt4 + 1][1],
                        uBh + off);
            }
            #pragma unroll
            for (int mt = 0; mt < 2; mt++)
                #pragma unroll
                for (int nt = 0; nt < 8; nt++) {
                    mma_f16(c[mt][nt], ah[mt], bh[nt]);
                    if (TWO) mma_f16(c[mt][nt], al[mt], bh[nt]);
                }
        }
        __syncthreads();
    }

    // ---- epilogue: fp16 out ----
    #pragma unroll
    for (int mt = 0; mt < 2; mt++) {
        int gr0 = row0 + wm + mt * 16 + g;
        int gr1 = gr0 + 8;
        #pragma unroll
        for (int nt = 0; nt < 8; nt++) {
            int cc = wn + nt * 8 + 2 * tig;
            if (gr0 < M) *(__half2*)(C + (size_t)gr0 * 128 + cc) = __floats2half2_rn(c[mt][nt][0], c[mt][nt][1]);
            if (gr1 < M) *(__half2*)(C + (size_t)gr1 * 128 + cc) = __floats2half2_rn(c[mt][nt][2], c[mt][nt][3]);
        }
    }
}

__global__ __launch_bounds__(256) void gemm_f32A(const float* __restrict__ A,
                                                 const __half* __restrict__ Bh,
                                                 __half* __restrict__ C, int M, int K) {
    gemm_body<true, false>(A, nullptr, Bh, C, M, K);
}
__global__ __launch_bounds__(256) void gemm_f16A(const __half* __restrict__ Ah,
                                                 const __half* __restrict__ Al,
                                                 const __half* __restrict__ Bh,
                                                 __half* __restrict__ C, int M, int K) {
    gemm_body<false, true>(Ah, Al, Bh, C, M, K);
}

// ---------------- aggregation: one warp per node, CSR gather of fp16 rows ----------------
__device__ __forceinline__ float4 load_row4(const __half* __restrict__ in, int node, int lane) {
    uint2 pv = ((const uint2*)(in + (size_t)node * HIDF))[lane];  // 4 halves
    float2 fa = __half22float2(*(__half2*)&pv.x);
    float2 fb = __half22float2(*(__half2*)&pv.y);
    return make_float4(fa.x, fa.y, fb.x, fb.y);
}

// Layer 1: relu, emit fp16 hi/lo split (feeds gemm_f16A)
__global__ __launch_bounds__(256) void k_agg_f16(const __half* __restrict__ in,
                                                 __half* __restrict__ outh,
                                                 __half* __restrict__ outl,
                                                 const float* __restrict__ bias) {
    int warp = (blockIdx.x * blockDim.x + threadIdx.x) >> 5;
    int lane = threadIdx.x & 31;
    if (warp >= NN) return;
    float dn = g_dinv[warp];
    float4 v = load_row4(in, warp, lane);
    float s = dn * dn;
    float4 acc = make_float4(v.x * s, v.y * s, v.z * s, v.w * s);
    int beg = g_rowptr[warp], end = g_rowptr[warp + 1];
    for (int j = beg; j < end; j++) {
        int src = g_src[j];
        float w = g_dinv[src] * dn;
        float4 u = load_row4(in, src, lane);
        acc.x += u.x * w; acc.y += u.y * w;
        acc.z += u.z * w; acc.w += u.w * w;
    }
    float4 b = ((const float4*)bias)[lane];
    acc.x = fmaxf(acc.x + b.x, 0.f); acc.y = fmaxf(acc.y + b.y, 0.f);
    acc.z = fmaxf(acc.z + b.z, 0.f); acc.w = fmaxf(acc.w + b.w, 0.f);
    __half hx = __float2half_rn(acc.x), hy = __float2half_rn(acc.y);
    __half hz = __float2half_rn(acc.z), hw = __float2half_rn(acc.w);
    __half2 h0 = __halves2half2(hx, hy), h1 = __halves2half2(hz, hw);
    __half2 l0 = __halves2half2(__float2half_rn(acc.x - __half2float(hx)),
                                __float2half_rn(acc.y - __half2float(hy)));
    __half2 l1 = __halves2half2(__float2half_rn(acc.z - __half2float(hz)),
                                __float2half_rn(acc.w - __half2float(hw)));
    uint2 ph = make_uint2(*(uint32_t*)&h0, *(uint32_t*)&h1);
    uint2 pl = make_uint2(*(uint32_t*)&l0, *(uint32_t*)&l1);
    ((uint2*)(outh + (size_t)warp * HIDF))[lane] = ph;
    ((uint2*)(outl + (size_t)warp * HIDF))[lane] = pl;
}

// Layer 2: fp32 out (final h), no relu
__global__ __launch_bounds__(256) void k_agg_f32(const __half* __restrict__ in,
                                                 float* __restrict__ out,
                                                 const float* __restrict__ bias) {
    int warp = (blockIdx.x * blockDim.x + threadIdx.x) >> 5;
    int lane = threadIdx.x & 31;
    if (warp >= NN) return;
    float dn = g_dinv[warp];
    float4 v = load_row4(in, warp, lane);
    float s = dn * dn;
    float4 acc = make_float4(v.x * s, v.y * s, v.z * s, v.w * s);
    int beg = g_rowptr[warp], end = g_rowptr[warp + 1];
    for (int j = beg; j < end; j++) {
        int src = g_src[j];
        float w = g_dinv[src] * dn;
        float4 u = load_row4(in, src, lane);
        acc.x += u.x * w; acc.y += u.y * w;
        acc.z += u.z * w; acc.w += u.w * w;
    }
    float4 b = ((const float4*)bias)[lane];
    acc.x += b.x; acc.y += b.y; acc.z += b.z; acc.w += b.w;
    ((float4*)(out + (size_t)warp * HIDF))[lane] = acc;
}

// ---------------- global_add_pool: batch is sorted -> segmented sum ----------------
__global__ void k_pool(const float* __restrict__ h, const int* __restrict__ batch,
                       float* __restrict__ out) {
    int g = blockIdx.x;
    int t = threadIdx.x;
    int a = 0, b = NN;
    while (a < b) { int m = (a + b) >> 1; if (batch[m] < g) a = m + 1; else b = m; }
    int s = a;
    a = 0; b = NN;
    while (a < b) { int m = (a + b) >> 1; if (batch[m] < g + 1) a = m + 1; else b = m; }
    int e = a;
    float acc = 0.f;
    for (int n = s; n < e; n++) acc += h[(size_t)n * HIDF + t];
    out[(size_t)g * HIDF + t] = acc;
}

// ---------------- launch ----------------
extern "C" void kernel_launch(void* const* d_in, const int* in_sizes, int n_in,
                              void* d_out, int out_size) {
    const float* x     = (const float*)d_in[0];
    const float* W1    = (const float*)d_in[1];
    const float* b1    = (const float*)d_in[2];
    const float* W2    = (const float*)d_in[3];
    const float* b2    = (const float*)d_in[4];
    const int*   ei    = (const int*)d_in[5];
    const int*   batch = (const int*)d_in[6];
    const int* row = ei;        // edge_index[0] = source
    const int* col = ei + NE;   // edge_index[1] = target

    float* out_hs = (float*)d_out;
    float* out_h  = (float*)d_out + (size_t)NG * HIDF;

    __half *g1, *h1h, *h1l, *w1h, *w2h;
    cudaGetSymbolAddress((void**)&g1, g_g1);
    cudaGetSymbolAddress((void**)&h1h, g_h1h);
    cudaGetSymbolAddress((void**)&h1l, g_h1l);
    cudaGetSymbolAddress((void**)&w1h, g_w1h);
    cudaGetSymbolAddress((void**)&w2h, g_w2h);

    // idempotent, not a stream op — safe under graph capture, no static guard
    cudaFuncSetAttribute(k_scan, cudaFuncAttributeMaxDynamicSharedMemorySize, NN * 4);

    // preprocessing
    k_prepw<<<256, 256>>>(W1, W2);
    k_count<<<(NE / 2 + 255) / 256, 256>>>(col);
    k_scan<<<1, 1024, NN * 4>>>();
    k_fill<<<(NE / 2 + 255) / 256, 256>>>(row, col);

    const int GEMM_GRID = (NN + 127) / 128;  // 391
    const int AGG_GRID  = (NN + 7) / 8;      // 6250

    // layer 1
    gemm_f32A<<<GEMM_GRID, 256>>>(x, w1h, g1, NN, INF_);
    k_agg_f16<<<AGG_GRID, 256>>>(g1, h1h, h1l, b1);

    // layer 2
    gemm_f16A<<<GEMM_GRID, 256>>>(h1h, h1l, w2h, g1, NN, HIDF);
    k_agg_f32<<<AGG_GRID, 256>>>(g1, out_h, b2);

    // pooling
    k_pool<<<NG, 128>>>(out_h, batch, out_hs);
}

// round 10
// speedup vs baseline: 2.6648x; 1.1390x over previous
#include <cuda_runtime.h>
#include <cuda_fp16.h>
#include <cstdint>
#include <cstddef>

#define NN   50000
#define NE   640000
#define INF_ 512
#define HIDF 128
#define NG   256

// ---------------- device scratch (no allocations allowed) ----------------
__device__ int   g_cnt[NN];          // zero at load; k_scan restores to zero each launch
__device__ float g_dinv[NN];
__device__ int   g_rowptr[NN + 1];
__device__ int   g_rank[NE];
__device__ int   g_src[NE];
__device__ __half g_g1[(size_t)NN * HIDF];    // gemm outputs (fp16), reused both layers
__device__ __half g_h1h[(size_t)NN * HIDF];   // layer-1 agg output (fp16)
// transposed fp16 weights: Wt[n][k] = W[k][n]
__device__ __half g_w1h[128 * 512];
__device__ __half g_w2h[128 * 128];

// ---------------- helpers ----------------
__device__ __forceinline__ uint32_t smem_u32(const void* p) {
    uint32_t a;
    asm("{ .reg .u64 t; cvta.to.shared.u64 t, %1; cvt.u32.u64 %0, t; }" : "=r"(a) : "l"(p));
    return a;
}
__device__ __forceinline__ void ldsm_x4(uint32_t& r0, uint32_t& r1, uint32_t& r2, uint32_t& r3,
                                        uint32_t addr) {
    asm volatile("ldmatrix.sync.aligned.m8n8.x4.shared.b16 {%0,%1,%2,%3}, [%4];"
                 : "=r"(r0), "=r"(r1), "=r"(r2), "=r"(r3) : "r"(addr));
}
__device__ __forceinline__ void mma_f16(float* c, const uint32_t* a, const uint32_t* b) {
    asm volatile(
        "mma.sync.aligned.m16n8k16.row.col.f32.f16.f16.f32 "
        "{%0,%1,%2,%3}, {%4,%5,%6,%7}, {%8,%9}, {%0,%1,%2,%3};"
        : "+f"(c[0]), "+f"(c[1]), "+f"(c[2]), "+f"(c[3])
        : "r"(a[0]), "r"(a[1]), "r"(a[2]), "r"(a[3]), "r"(b[0]), "r"(b[1]));
}

// ---------------- preprocessing ----------------
// transpose/cast weights (g_cnt zeroing handled by k_scan's restore)
__global__ void k_prepw(const float* __restrict__ W1, const float* __restrict__ W2) {
    int i = blockIdx.x * blockDim.x + threadIdx.x;
    if (i < 128 * 512) {
        int n = i >> 9, k = i & 511;
        g_w1h[i] = __float2half_rn(W1[k * 128 + n]);
    }
    if (i < 128 * 128) {
        int n = i >> 7, k = i & 127;
        g_w2h[i] = __float2half_rn(W2[k * 128 + n]);
    }
}

// count + record per-edge rank within destination (atomicAdd return value), 2 edges/thread
__global__ void k_count(const int* __restrict__ col) {
    int t = blockIdx.x * blockDim.x + threadIdx.x;
    if (t < NE / 2) {
        int2 c2 = ((const int2*)col)[t];
        int2 r;
        r.x = atomicAdd(&g_cnt[c2.x], 1);
        r.y = atomicAdd(&g_cnt[c2.y], 1);
        ((int2*)g_rank)[t] = r;
    }
}

// single-block scan, smem-staged for fully coalesced global access.
// Also restores g_cnt to zero for the next launch (invariant: zero at entry).
__global__ __launch_bounds__(1024) void k_scan() {
    extern __shared__ int sc[];   // NN ints = 200 000 B
    __shared__ int wsum[32];
    int t = threadIdx.x, lane = t & 31, w = t >> 5;
    for (int i = t; i < NN; i += 1024) {
        int c = g_cnt[i];
        sc[i] = c;
        g_dinv[i] = rsqrtf((float)(c + 1));  // +1 self-loop
        g_cnt[i] = 0;                        // restore invariant for next launch
    }
    __syncthreads();
    const int SEG = (NN + 1023) / 1024;  // 49
    int s0 = t * SEG, s1 = s0 + SEG;
    if (s1 > NN) s1 = NN;
    if (s0 > NN) s0 = NN;
    int s = 0;
    for (int i = s0; i < s1; i++) s += sc[i];
    int v = s;
    #pragma unroll
    for (int o = 1; o < 32; o <<= 1) {
        int u = __shfl_up_sync(0xFFFFFFFFu, v, o);
        if (lane >= o) v += u;
    }
    if (lane == 31) wsum[w] = v;
    __syncthreads();
    if (w == 0) {
        int x = wsum[lane];
        #pragma unroll
        for (int o = 1; o < 32; o <<= 1) {
            int u = __shfl_up_sync(0xFFFFFFFFu, x, o);
            if (lane >= o) x += u;
        }
        wsum[lane] = x;
    }
    __syncthreads();
    int P = v - s + (w > 0 ? wsum[w - 1] : 0);
    for (int i = s0; i < s1; i++) {
        int c = sc[i];
        sc[i] = P;     // in-place exclusive prefix
        P += c;
    }
    __syncthreads();
    for (int i = t; i < NN; i += 1024) g_rowptr[i] = sc[i];
    if (t == 0) g_rowptr[NN] = wsum[31];
}

// atomic-free fill using precomputed ranks, 2 edges/thread
__global__ void k_fill(const int* __restrict__ row, const int* __restrict__ col) {
    int t = blockIdx.x * blockDim.x + threadIdx.x;
    if (t < NE / 2) {
        int2 r2 = ((const int2*)row)[t];
        int2 c2 = ((const int2*)col)[t];
        int2 k2 = ((const int2*)g_rank)[t];
        g_src[g_rowptr[c2.x] + k2.x] = r2.x;
        g_src[g_rowptr[c2.y] + k2.y] = r2.y;
    }
}

// ---------------- HMMA GEMM: C[M,128] = A[M,K] @ Wt^T, fp16 out ----------------
// F32A: A fp32 -> fp16 in-kernel (layer 1). !F32A: A already fp16 (layer 2).
#define ASTRIDE 40  // fp16 elems per smem row (80 B), conflict-free ldmatrix

template <bool F32A>
__device__ __forceinline__ void gemm_body(const void* __restrict__ Aptr,
                                          const __half* __restrict__ Bh,
                                          __half* __restrict__ C,
                                          int M, int K) {
    __shared__ __half sAh[128 * ASTRIDE];
    __shared__ __half sBh[128 * ASTRIDE];
    const int tid = threadIdx.x;
    const int wid = tid >> 5, lane = tid & 31;
    const int wm = (wid >> 1) * 32;
    const int wn = (wid & 1) * 64;
    const int g = lane >> 2, tig = lane & 3;
    const int row0 = blockIdx.x * 128;

    const uint32_t uAh = smem_u32(sAh);
    const uint32_t uBh = smem_u32(sBh);

    float c[2][8][4];
    #pragma unroll
    for (int mt = 0; mt < 2; mt++)
        #pragma unroll
        for (int nt = 0; nt < 8; nt++)
            #pragma unroll
            for (int q = 0; q < 4; q++) c[mt][nt][q] = 0.f;

    const int nch = K >> 5;

    float4 pa[4];
    uint4 pah[2];
    uint4 pbh[2];

    // ---- load chunk 0 ----
    if (F32A) {
        const float* A = (const float*)Aptr;
        #pragma unroll
        for (int i = 0; i < 4; i++) {
            int q = i * 256 + tid;
            int r = q >> 3, c4 = q & 7;
            int gr = row0 + r;
            pa[i] = (gr < M) ? *(const float4*)(A + (size_t)gr * K + c4 * 4)
                             : make_float4(0.f, 0.f, 0.f, 0.f);
        }
    } else {
        const __half* Ah = (const __half*)Aptr;
        #pragma unroll
        for (int i = 0; i < 2; i++) {
            int q = i * 256 + tid;
            int r = q >> 2, c16 = q & 3;
            int gr = row0 + r;
            pah[i] = (gr < M) ? *(const uint4*)(Ah + (size_t)gr * K + c16 * 8)
                              : make_uint4(0, 0, 0, 0);
        }
    }
    #pragma unroll
    for (int i = 0; i < 2; i++) {
        int q = i * 256 + tid;
        int r = q >> 2, c16 = q & 3;
        pbh[i] = *(const uint4*)(Bh + (size_t)r * K + c16 * 8);
    }

    for (int ch = 0; ch < nch; ch++) {
        if (F32A) {
            #pragma unroll
            for (int i = 0; i < 4; i++) {
                int q = i * 256 + tid;
                int r = q >> 3, c4 = q & 7;
                float4 v = pa[i];
                __half2 h0 = __floats2half2_rn(v.x, v.y);
                __half2 h1 = __floats2half2_rn(v.z, v.w);
                int e = r * ASTRIDE + c4 * 4;
                *(uint32_t*)((char*)sAh + e * 2)     = *(uint32_t*)&h0;
                *(uint32_t*)((char*)sAh + e * 2 + 4) = *(uint32_t*)&h1;
            }
        } else {
            #pragma unroll
            for (int i = 0; i < 2; i++) {
                int q = i * 256 + tid;
                int r = q >> 2, c16 = q & 3;
                int e = r * ASTRIDE + c16 * 8;
                *(uint4*)((char*)sAh + e * 2) = pah[i];
            }
        }
        #pragma unroll
        for (int i = 0; i < 2; i++) {
            int q = i * 256 + tid;
            int r = q >> 2, c16 = q & 3;
            int e = r * ASTRIDE + c16 * 8;
            *(uint4*)((char*)sBh + e * 2) = pbh[i];
        }
        __syncthreads();

        if (ch + 1 < nch) {
            int k0 = (ch + 1) << 5;
            if (F32A) {
                const float* A = (const float*)Aptr;
                #pragma unroll
                for (int i = 0; i < 4; i++) {
                    int q = i * 256 + tid;
                    int r = q >> 3, c4 = q & 7;
                    int gr = row0 + r;
                    pa[i] = (gr < M) ? *(const float4*)(A + (size_t)gr * K + k0 + c4 * 4)
                                     : make_float4(0.f, 0.f, 0.f, 0.f);
                }
            } else {
                const __half* Ah = (const __half*)Aptr;
                #pragma unroll
                for (int i = 0; i < 2; i++) {
                    int q = i * 256 + tid;
                    int r = q >> 2, c16 = q & 3;
                    int gr = row0 + r;
                    pah[i] = (gr < M) ? *(const uint4*)(Ah + (size_t)gr * K + k0 + c16 * 8)
                                      : make_uint4(0, 0, 0, 0);
                }
            }
            #pragma unroll
            for (int i = 0; i < 2; i++) {
                int q = i * 256 + tid;
                int r = q >> 2, c16 = q & 3;
                pbh[i] = *(const uint4*)(Bh + (size_t)r * K + k0 + c16 * 8);
            }
        }

        #pragma unroll
        for (int ks = 0; ks < 2; ks++) {
            const int kc = ks * 16 + ((lane & 16) ? 8 : 0);
            uint32_t ah[2][4];
            #pragma unroll
            for (int mt = 0; mt < 2; mt++) {
                int r = wm + mt * 16 + (lane & 15);
                uint32_t off = (uint32_t)(r * ASTRIDE + kc) * 2;
                ldsm_x4(ah[mt][0], ah[mt][1], ah[mt][2], ah[mt][3], uAh + off);
            }
            uint32_t bh[8][2];
            const int kcb = ks * 16 + ((lane & 8) ? 8 : 0);
            #pragma unroll
            for (int nt4 = 0; nt4 < 4; nt4++) {
                int n = wn + nt4 * 16 + ((lane & 7) | ((lane & 16) ? 8 : 0));
                uint32_t off = (uint32_t)(n * ASTRIDE + kcb) * 2;
                ldsm_x4(bh[2 * nt4][0], bh[2 * nt4][1], bh[2 * nt4 + 1][0], bh[2 * nt4 + 1][1],
                        uBh + off);
            }
            #pragma unroll
            for (int mt = 0; mt < 2; mt++)
                #pragma unroll
                for (int nt = 0; nt < 8; nt++)
                    mma_f16(c[mt][nt], ah[mt], bh[nt]);
        }
        __syncthreads();
    }

    // ---- epilogue: fp16 out ----
    #pragma unroll
    for (int mt = 0; mt < 2; mt++) {
        int gr0 = row0 + wm + mt * 16 + g;
        int gr1 = gr0 + 8;
        #pragma unroll
        for (int nt = 0; nt < 8; nt++) {
            int cc = wn + nt * 8 + 2 * tig;
            if (gr0 < M) *(__half2*)(C + (size_t)gr0 * 128 + cc) = __floats2half2_rn(c[mt][nt][0], c[mt][nt][1]);
            if (gr1 < M) *(__half2*)(C + (size_t)gr1 * 128 + cc) = __floats2half2_rn(c[mt][nt][2], c[mt][nt][3]);
        }
    }
}

__global__ __launch_bounds__(256) void gemm_f32A(const float* __restrict__ A,
                                                 const __half* __restrict__ Bh,
                                                 __half* __restrict__ C, int M, int K) {
    gemm_body<true>(A, Bh, C, M, K);
}
__global__ __launch_bounds__(256) void gemm_f16A(const __half* __restrict__ Ah,
                                                 const __half* __restrict__ Bh,
                                                 __half* __restrict__ C, int M, int K) {
    gemm_body<false>(Ah, Bh, C, M, K);
}

// ---------------- aggregation: one warp per node, CSR gather of fp16 rows ----------------
__device__ __forceinline__ float4 load_row4(const __half* __restrict__ in, int node, int lane) {
    uint2 pv = ((const uint2*)(in + (size_t)node * HIDF))[lane];  // 4 halves
    float2 fa = __half22float2(*(__half2*)&pv.x);
    float2 fb = __half22float2(*(__half2*)&pv.y);
    return make_float4(fa.x, fa.y, fb.x, fb.y);
}

// Layer 1: relu, emit fp16 (feeds gemm_f16A)
__global__ __launch_bounds__(256) void k_agg_f16(const __half* __restrict__ in,
                                                 __half* __restrict__ outh,
                                                 const float* __restrict__ bias) {
    int warp = (blockIdx.x * blockDim.x + threadIdx.x) >> 5;
    int lane = threadIdx.x & 31;
    if (warp >= NN) return;
    float dn = g_dinv[warp];
    float4 v = load_row4(in, warp, lane);
    float s = dn * dn;
    float4 acc = make_float4(v.x * s, v.y * s, v.z * s, v.w * s);
    int beg = g_rowptr[warp], end = g_rowptr[warp + 1];
    for (int j = beg; j < end; j++) {
        int src = g_src[j];
        float w = g_dinv[src] * dn;
        float4 u = load_row4(in, src, lane);
        acc.x += u.x * w; acc.y += u.y * w;
        acc.z += u.z * w; acc.w += u.w * w;
    }
    float4 b = ((const float4*)bias)[lane];
    acc.x = fmaxf(acc.x + b.x, 0.f); acc.y = fmaxf(acc.y + b.y, 0.f);
    acc.z = fmaxf(acc.z + b.z, 0.f); acc.w = fmaxf(acc.w + b.w, 0.f);
    __half2 h0 = __floats2half2_rn(acc.x, acc.y);
    __half2 h1 = __floats2half2_rn(acc.z, acc.w);
    uint2 ph = make_uint2(*(uint32_t*)&h0, *(uint32_t*)&h1);
    ((uint2*)(outh + (size_t)warp * HIDF))[lane] = ph;
}

// Layer 2: fp32 out (final h), no relu
__global__ __launch_bounds__(256) void k_agg_f32(const __half* __restrict__ in,
                                                 float* __restrict__ out,
                                                 const float* __restrict__ bias) {
    int warp = (blockIdx.x * blockDim.x + threadIdx.x) >> 5;
    int lane = threadIdx.x & 31;
    if (warp >= NN) return;
    float dn = g_dinv[warp];
    float4 v = load_row4(in, warp, lane);
    float s = dn * dn;
    float4 acc = make_float4(v.x * s, v.y * s, v.z * s, v.w * s);
    int beg = g_rowptr[warp], end = g_rowptr[warp + 1];
    for (int j = beg; j < end; j++) {
        int src = g_src[j];
        float w = g_dinv[src] * dn;
        float4 u = load_row4(in, src, lane);
        acc.x += u.x * w; acc.y += u.y * w;
        acc.z += u.z * w; acc.w += u.w * w;
    }
    float4 b = ((const float4*)bias)[lane];
    acc.x += b.x; acc.y += b.y; acc.z += b.z; acc.w += b.w;
    ((float4*)(out + (size_t)warp * HIDF))[lane] = acc;
}

// ---------------- global_add_pool: batch is sorted -> segmented sum ----------------
__global__ void k_pool(const float* __restrict__ h, const int* __restrict__ batch,
                       float* __restrict__ out) {
    int g = blockIdx.x;
    int t = threadIdx.x;
    int a = 0, b = NN;
    while (a < b) { int m = (a + b) >> 1; if (batch[m] < g) a = m + 1; else b = m; }
    int s = a;
    a = 0; b = NN;
    while (a < b) { int m = (a + b) >> 1; if (batch[m] < g + 1) a = m + 1; else b = m; }
    int e = a;
    float acc = 0.f;
    for (int n = s; n < e; n++) acc += h[(size_t)n * HIDF + t];
    out[(size_t)g * HIDF + t] = acc;
}

// ---------------- launch ----------------
extern "C" void kernel_launch(void* const* d_in, const int* in_sizes, int n_in,
                              void* d_out, int out_size) {
    const float* x     = (const float*)d_in[0];
    const float* W1    = (const float*)d_in[1];
    const float* b1    = (const float*)d_in[2];
    const float* W2    = (const float*)d_in[3];
    const float* b2    = (const float*)d_in[4];
    const int*   ei    = (const int*)d_in[5];
    const int*   batch = (const int*)d_in[6];
    const int* row = ei;        // edge_index[0] = source
    const int* col = ei + NE;   // edge_index[1] = target

    float* out_hs = (float*)d_out;
    float* out_h  = (float*)d_out + (size_t)NG * HIDF;

    __half *g1, *h1h, *w1h, *w2h;
    cudaGetSymbolAddress((void**)&g1, g_g1);
    cudaGetSymbolAddress((void**)&h1h, g_h1h);
    cudaGetSymbolAddress((void**)&w1h, g_w1h);
    cudaGetSymbolAddress((void**)&w2h, g_w2h);

    // idempotent, not a stream op — safe under graph capture
    cudaFuncSetAttribute(k_scan, cudaFuncAttributeMaxDynamicSharedMemorySize, NN * 4);

    // Fork a second stream so the CSR build overlaps prepw+GEMM1 in the captured
    // graph. Standard event fork-join; objects are created per call and not
    // destroyed (kernel_launch runs only for the correctness pass + the capture
    // pass, and destroying capture-referenced objects mid-capture is unsafe).
    cudaStream_t s2;
    cudaStreamCreateWithFlags(&s2, cudaStreamNonBlocking);
    cudaEvent_t evFork, evJoin;
    cudaEventCreateWithFlags(&evFork, cudaEventDisableTiming);
    cudaEventCreateWithFlags(&evJoin, cudaEventDisableTiming);

    cudaEventRecord(evFork, 0);
    cudaStreamWaitEvent(s2, evFork, 0);

    // branch B (stream s2): CSR build
    k_count<<<(NE / 2 + 255) / 256, 256, 0, s2>>>(col);
    k_scan<<<1, 1024, NN * 4, s2>>>();
    k_fill<<<(NE / 2 + 255) / 256, 256, 0, s2>>>(row, col);
    cudaEventRecord(evJoin, s2);

    const int GEMM_GRID = (NN + 127) / 128;  // 391
    const int AGG_GRID  = (NN + 7) / 8;      // 6250

    // branch A (origin stream): weights + layer-1 GEMM
    k_prepw<<<256, 256>>>(W1, W2);
    gemm_f32A<<<GEMM_GRID, 256>>>(x, w1h, g1, NN, INF_);

    // join: aggregation needs the CSR
    cudaStreamWaitEvent(0, evJoin, 0);
    k_agg_f16<<<AGG_GRID, 256>>>(g1, h1h, b1);

    // layer 2
    gemm_f16A<<<GEMM_GRID, 256>>>(h1h, w2h, g1, NN, HIDF);
    k_agg_f32<<<AGG_GRID, 256>>>(g1, out_h, b2);

    // pooling
    k_pool<<<NG, 128>>>(out_h, batch, out_hs);
}